// round 1
// baseline (speedup 1.0000x reference)
#include <cuda_runtime.h>
#include <cuda_bf16.h>
#include <math.h>

// ---------------------------------------------------------------------------
// Problem constants: B=8, S=1024, D=1024, H=16, DK=64, MLP=4096
// tokens = 8192
// ---------------------------------------------------------------------------
#define TOK   8192
#define DMODEL 1024
#define NHEAD 16
#define DKH   64
#define DMLP  4096

// ---------------------------------------------------------------------------
// Scratch (device globals; no allocation allowed)
// ---------------------------------------------------------------------------
__device__ float g_h   [TOK * DMODEL];   // ln1 output
__device__ float g_q   [TOK * DMODEL];
__device__ float g_k   [TOK * DMODEL];
__device__ float g_v   [TOK * DMODEL];
__device__ float g_ctx [TOK * DMODEL];   // attention context
__device__ float g_out1[TOK * DMODEL];   // x + relu(ctx@wo+bo)
__device__ float g_h2  [TOK * DMODEL];   // ln2 output
__device__ float g_ff  [TOK * DMLP];     // gelu(h2@w1+b1)

// ---------------------------------------------------------------------------
// LayerNorm: one block per row (D=1024), 256 threads, float4
// ---------------------------------------------------------------------------
__global__ __launch_bounds__(256) void ln_kernel(
    const float* __restrict__ x, const float* __restrict__ w,
    const float* __restrict__ b, float* __restrict__ out)
{
    int row = blockIdx.x;
    int tid = threadIdx.x;
    const float4* xr = (const float4*)(x + (size_t)row * DMODEL);
    float4 v = xr[tid];
    float s  = v.x + v.y + v.z + v.w;
    float sq = v.x*v.x + v.y*v.y + v.z*v.z + v.w*v.w;
    #pragma unroll
    for (int o = 16; o; o >>= 1) {
        s  += __shfl_xor_sync(0xffffffffu, s,  o);
        sq += __shfl_xor_sync(0xffffffffu, sq, o);
    }
    __shared__ float ss[8], ssq[8];
    __shared__ float s_mu, s_r;
    if ((tid & 31) == 0) { ss[tid >> 5] = s; ssq[tid >> 5] = sq; }
    __syncthreads();
    if (tid == 0) {
        float S = 0.f, Q = 0.f;
        #pragma unroll
        for (int i = 0; i < 8; i++) { S += ss[i]; Q += ssq[i]; }
        float mu  = S * (1.0f / DMODEL);
        float var = Q * (1.0f / DMODEL) - mu * mu;
        s_mu = mu;
        s_r  = rsqrtf(var + 1e-5f);
    }
    __syncthreads();
    float mu = s_mu, r = s_r;
    float4 w4 = ((const float4*)w)[tid];
    float4 b4 = ((const float4*)b)[tid];
    float4 o4;
    o4.x = (v.x - mu) * r * w4.x + b4.x;
    o4.y = (v.y - mu) * r * w4.y + b4.y;
    o4.z = (v.z - mu) * r * w4.z + b4.z;
    o4.w = (v.w - mu) * r * w4.w + b4.w;
    ((float4*)(out + (size_t)row * DMODEL))[tid] = o4;
}

// ---------------------------------------------------------------------------
// SGEMM: C[M,N] = A[M,K] @ B[K,N] + bias, epilogue modes:
//   0: none   1: relu(v)+res   2: gelu(v)   3: v+res
// 128x128 block tile, 8x8 per thread, BK=8, 256 threads.
// ---------------------------------------------------------------------------
__global__ __launch_bounds__(256) void sgemm_kernel(
    const float* __restrict__ A, const float* __restrict__ B,
    const float* __restrict__ bias, const float* __restrict__ res,
    float* __restrict__ C, int M, int N, int K, int mode)
{
    __shared__ float As[8][128];
    __shared__ float Bs[8][128];

    int tid = threadIdx.x;
    int tx = tid & 15;    // n-dir thread coord
    int ty = tid >> 4;    // m-dir thread coord
    int bn = blockIdx.x * 128;
    int bm = blockIdx.y * 128;

    int aRow = tid >> 1;
    int aCol = (tid & 1) * 4;
    int bRow = tid >> 5;
    int bCol = (tid & 31) * 4;

    const float* Ap = A + (size_t)(bm + aRow) * K + aCol;
    const float* Bp = B + (size_t)bRow * N + bn + bCol;

    float acc[8][8];
    #pragma unroll
    for (int i = 0; i < 8; i++)
        #pragma unroll
        for (int j = 0; j < 8; j++) acc[i][j] = 0.f;

    int nk = K >> 3;
    for (int t = 0; t < nk; t++) {
        float4 a4 = *(const float4*)Ap;
        float4 b4 = *(const float4*)Bp;
        As[aCol + 0][aRow] = a4.x;
        As[aCol + 1][aRow] = a4.y;
        As[aCol + 2][aRow] = a4.z;
        As[aCol + 3][aRow] = a4.w;
        *(float4*)&Bs[bRow][bCol] = b4;
        __syncthreads();
        Ap += 8;
        Bp += (size_t)8 * N;
        #pragma unroll
        for (int k = 0; k < 8; k++) {
            float ra[8], rb[8];
            *(float4*)(ra)     = *(const float4*)&As[k][ty * 4];
            *(float4*)(ra + 4) = *(const float4*)&As[k][64 + ty * 4];
            *(float4*)(rb)     = *(const float4*)&Bs[k][tx * 4];
            *(float4*)(rb + 4) = *(const float4*)&Bs[k][64 + tx * 4];
            #pragma unroll
            for (int i = 0; i < 8; i++)
                #pragma unroll
                for (int j = 0; j < 8; j++)
                    acc[i][j] += ra[i] * rb[j];
        }
        __syncthreads();
    }

    #pragma unroll
    for (int i = 0; i < 8; i++) {
        int row = bm + ((i < 4) ? (ty * 4 + i) : (60 + ty * 4 + i));
        const float* resr = res + (size_t)row * N + bn;  // only deref when mode uses it
        float* cr = C + (size_t)row * N + bn;
        #pragma unroll
        for (int jh = 0; jh < 2; jh++) {
            int cl = jh * 64 + tx * 4;
            float4 outv;
            float* po = &outv.x;
            #pragma unroll
            for (int j = 0; j < 4; j++) {
                float v = acc[i][jh * 4 + j] + bias[bn + cl + j];
                if (mode == 1)      v = fmaxf(v, 0.f) + resr[cl + j];
                else if (mode == 2) v = 0.5f * v * (1.f + erff(v * 0.70710678118654752f));
                else if (mode == 3) v = v + resr[cl + j];
                po[j] = v;
            }
            *(float4*)(cr + cl) = outv;
        }
    }
}

// ---------------------------------------------------------------------------
// Flash attention (fp32): grid (S/64, B*H), 256 threads (8 warps).
// Q tile 64 rows (scaled by 1/8 at load), KV tiles of 64 keys.
// K in smem at pitch 68 (16B aligned, conflict-free float4 reads).
// V stored transposed (sVt[d][j], pitch 68) so PV is float4 over j.
// P reuses the K smem slab. Online softmax in registers.
// Layout: [B, S, D] with heads interleaved (row stride D=1024).
// ---------------------------------------------------------------------------
#define ATTN_SMEM_FLOATS (64*64 + 64*68 + 64*68)   // 12800 floats = 51200 B

__global__ __launch_bounds__(256) void attn_kernel(
    const float* __restrict__ Qg, const float* __restrict__ Kg,
    const float* __restrict__ Vg, float* __restrict__ Og)
{
    extern __shared__ float sm[];
    float* sQ  = sm;                 // 64 x 64
    float* sK  = sm + 64 * 64;       // 64 x 68  (reused as P)
    float* sVt = sK + 64 * 68;       // 64 x 68  (transposed: [d][j])

    int bh = blockIdx.y;
    int b  = bh >> 4;
    int h  = bh & 15;
    int q0 = blockIdx.x * 64;

    size_t base = (size_t)b * 1024 * DMODEL + (size_t)h * DKH;
    const float* Qb = Qg + base;
    const float* Kb = Kg + base;
    const float* Vb = Vg + base;
    float*       Ob = Og + base;

    int tid  = threadIdx.x;
    int lane = tid & 31;
    int w    = tid >> 5;
    int r0   = w * 8;

    int rr = tid >> 4;          // 0..15
    int cc = (tid & 15) * 4;    // 0..60

    // load Q tile, pre-scaled by 1/sqrt(DK) = 0.125
    #pragma unroll
    for (int it = 0; it < 4; it++) {
        int row = rr + it * 16;
        float4 v = *(const float4*)(Qb + (size_t)(q0 + row) * DMODEL + cc);
        v.x *= 0.125f; v.y *= 0.125f; v.z *= 0.125f; v.w *= 0.125f;
        *(float4*)(sQ + row * 64 + cc) = v;
    }

    float m[8], l[8], o0[8], o1[8];
    #pragma unroll
    for (int r = 0; r < 8; r++) { m[r] = -1e30f; l[r] = 0.f; o0[r] = 0.f; o1[r] = 0.f; }

    for (int kt = 0; kt < 16; kt++) {
        __syncthreads();   // prior P / Vt reads complete before overwrite
        #pragma unroll
        for (int it = 0; it < 4; it++) {
            int j = rr + it * 16;
            float4 kv = *(const float4*)(Kb + (size_t)(kt * 64 + j) * DMODEL + cc);
            *(float4*)(sK + j * 68 + cc) = kv;
            float4 vv = *(const float4*)(Vb + (size_t)(kt * 64 + j) * DMODEL + cc);
            sVt[(cc + 0) * 68 + j] = vv.x;
            sVt[(cc + 1) * 68 + j] = vv.y;
            sVt[(cc + 2) * 68 + j] = vv.z;
            sVt[(cc + 3) * 68 + j] = vv.w;
        }
        __syncthreads();

        // S = Q K^T  (rows r0..r0+7, cols lane & lane+32)
        float s0[8], s1[8];
        #pragma unroll
        for (int r = 0; r < 8; r++) { s0[r] = 0.f; s1[r] = 0.f; }
        #pragma unroll
        for (int d = 0; d < 64; d += 4) {
            float4 k0 = *(const float4*)(sK + lane * 68 + d);
            float4 k1 = *(const float4*)(sK + (lane + 32) * 68 + d);
            #pragma unroll
            for (int r = 0; r < 8; r++) {
                float4 q4 = *(const float4*)(sQ + (r0 + r) * 64 + d);
                s0[r] += q4.x * k0.x + q4.y * k0.y + q4.z * k0.z + q4.w * k0.w;
                s1[r] += q4.x * k1.x + q4.y * k1.y + q4.z * k1.z + q4.w * k1.w;
            }
        }

        // online softmax update
        float p0[8], p1[8];
        #pragma unroll
        for (int r = 0; r < 8; r++) {
            float mx = fmaxf(s0[r], s1[r]);
            #pragma unroll
            for (int o = 16; o; o >>= 1)
                mx = fmaxf(mx, __shfl_xor_sync(0xffffffffu, mx, o));
            float mn = fmaxf(m[r], mx);
            float a  = __expf(m[r] - mn);
            p0[r] = __expf(s0[r] - mn);
            p1[r] = __expf(s1[r] - mn);
            float ps = p0[r] + p1[r];
            #pragma unroll
            for (int o = 16; o; o >>= 1)
                ps += __shfl_xor_sync(0xffffffffu, ps, o);
            l[r] = l[r] * a + ps;
            o0[r] *= a;
            o1[r] *= a;
            m[r] = mn;
        }

        __syncthreads();   // all sK reads done -> safe to overwrite with P
        #pragma unroll
        for (int r = 0; r < 8; r++) {
            sK[(r0 + r) * 68 + lane]      = p0[r];
            sK[(r0 + r) * 68 + lane + 32] = p1[r];
        }
        __syncthreads();

        // O += P @ V   (d = lane and lane+32)
        #pragma unroll
        for (int j = 0; j < 64; j += 4) {
            float4 v0 = *(const float4*)(sVt + lane * 68 + j);
            float4 v1 = *(const float4*)(sVt + (lane + 32) * 68 + j);
            #pragma unroll
            for (int r = 0; r < 8; r++) {
                float4 p4 = *(const float4*)(sK + (r0 + r) * 68 + j);
                o0[r] += p4.x * v0.x + p4.y * v0.y + p4.z * v0.z + p4.w * v0.w;
                o1[r] += p4.x * v1.x + p4.y * v1.y + p4.z * v1.z + p4.w * v1.w;
            }
        }
    }

    #pragma unroll
    for (int r = 0; r < 8; r++) {
        float inv = 1.f / l[r];
        size_t off = (size_t)(q0 + r0 + r) * DMODEL;
        Ob[off + lane]      = o0[r] * inv;
        Ob[off + lane + 32] = o1[r] * inv;
    }
}

// ---------------------------------------------------------------------------
// Host launcher
// ---------------------------------------------------------------------------
extern "C" void kernel_launch(void* const* d_in, const int* in_sizes, int n_in,
                              void* d_out, int out_size)
{
    const float* x     = (const float*)d_in[0];
    const float* ln1_w = (const float*)d_in[1];
    const float* ln1_b = (const float*)d_in[2];
    const float* wq    = (const float*)d_in[3];
    const float* bq    = (const float*)d_in[4];
    const float* wk    = (const float*)d_in[5];
    const float* bk    = (const float*)d_in[6];
    const float* wv    = (const float*)d_in[7];
    const float* bv    = (const float*)d_in[8];
    const float* wo    = (const float*)d_in[9];
    const float* bo    = (const float*)d_in[10];
    const float* ln2_w = (const float*)d_in[11];
    const float* ln2_b = (const float*)d_in[12];
    const float* w1    = (const float*)d_in[13];
    const float* b1    = (const float*)d_in[14];
    const float* w2    = (const float*)d_in[15];
    const float* b2    = (const float*)d_in[16];

    float *p_h, *p_q, *p_k, *p_v, *p_ctx, *p_out1, *p_h2, *p_ff;
    cudaGetSymbolAddress((void**)&p_h,    g_h);
    cudaGetSymbolAddress((void**)&p_q,    g_q);
    cudaGetSymbolAddress((void**)&p_k,    g_k);
    cudaGetSymbolAddress((void**)&p_v,    g_v);
    cudaGetSymbolAddress((void**)&p_ctx,  g_ctx);
    cudaGetSymbolAddress((void**)&p_out1, g_out1);
    cudaGetSymbolAddress((void**)&p_h2,   g_h2);
    cudaGetSymbolAddress((void**)&p_ff,   g_ff);

    cudaFuncSetAttribute(attn_kernel, cudaFuncAttributeMaxDynamicSharedMemorySize,
                         ATTN_SMEM_FLOATS * 4);

    // 1) ln1
    ln_kernel<<<TOK, 256>>>(x, ln1_w, ln1_b, p_h);
    // 2) QKV projections
    sgemm_kernel<<<dim3(8, 64), 256>>>(p_h, wq, bq, nullptr, p_q, TOK, DMODEL, DMODEL, 0);
    sgemm_kernel<<<dim3(8, 64), 256>>>(p_h, wk, bk, nullptr, p_k, TOK, DMODEL, DMODEL, 0);
    sgemm_kernel<<<dim3(8, 64), 256>>>(p_h, wv, bv, nullptr, p_v, TOK, DMODEL, DMODEL, 0);
    // 3) attention
    attn_kernel<<<dim3(16, 128), 256, ATTN_SMEM_FLOATS * 4>>>(p_q, p_k, p_v, p_ctx);
    // 4) out proj + relu + residual(x)
    sgemm_kernel<<<dim3(8, 64), 256>>>(p_ctx, wo, bo, x, p_out1, TOK, DMODEL, DMODEL, 1);
    // 5) ln2
    ln_kernel<<<TOK, 256>>>(p_out1, ln2_w, ln2_b, p_h2);
    // 6) MLP up + gelu
    sgemm_kernel<<<dim3(32, 64), 256>>>(p_h2, w1, b1, nullptr, p_ff, TOK, DMLP, DMODEL, 2);
    // 7) MLP down + residual(out1) -> d_out
    sgemm_kernel<<<dim3(8, 64), 256>>>(p_ff, w2, b2, p_out1, (float*)d_out, TOK, DMODEL, DMLP, 3);
}

// round 4
// speedup vs baseline: 1.3867x; 1.3867x over previous
#include <cuda_runtime.h>
#include <cuda_bf16.h>
#include <math.h>
#include <stdint.h>

// ---------------------------------------------------------------------------
// Problem constants: B=8, S=1024, D=1024, H=16, DK=64, MLP=4096, tokens=8192
// ---------------------------------------------------------------------------
#define TOK    8192
#define DMODEL 1024
#define NHEAD  16
#define DKH    64
#define DMLP   4096

// ---------------------------------------------------------------------------
// Scratch (device globals; no allocation allowed)
// ---------------------------------------------------------------------------
__device__ float g_h   [TOK * DMODEL];
__device__ float g_q   [TOK * DMODEL];
__device__ float g_k   [TOK * DMODEL];
__device__ float g_v   [TOK * DMODEL];
__device__ float g_ctx [TOK * DMODEL];
__device__ float g_out1[TOK * DMODEL];
__device__ float g_h2  [TOK * DMODEL];
__device__ float g_ff  [TOK * DMLP];

__device__ __forceinline__ uint32_t f2tf32(float x) {
    uint32_t r; asm("cvt.rna.tf32.f32 %0, %1;" : "=r"(r) : "f"(x)); return r;
}

// ---------------------------------------------------------------------------
// LayerNorm: one block per row (D=1024), 256 threads, float4
// ---------------------------------------------------------------------------
__global__ __launch_bounds__(256) void ln_kernel(
    const float* __restrict__ x, const float* __restrict__ w,
    const float* __restrict__ b, float* __restrict__ out)
{
    int row = blockIdx.x;
    int tid = threadIdx.x;
    const float4* xr = (const float4*)(x + (size_t)row * DMODEL);
    float4 v = xr[tid];
    float s  = v.x + v.y + v.z + v.w;
    float sq = v.x*v.x + v.y*v.y + v.z*v.z + v.w*v.w;
    #pragma unroll
    for (int o = 16; o; o >>= 1) {
        s  += __shfl_xor_sync(0xffffffffu, s,  o);
        sq += __shfl_xor_sync(0xffffffffu, sq, o);
    }
    __shared__ float ss[8], ssq[8];
    __shared__ float s_mu, s_r;
    if ((tid & 31) == 0) { ss[tid >> 5] = s; ssq[tid >> 5] = sq; }
    __syncthreads();
    if (tid == 0) {
        float S = 0.f, Q = 0.f;
        #pragma unroll
        for (int i = 0; i < 8; i++) { S += ss[i]; Q += ssq[i]; }
        float mu  = S * (1.0f / DMODEL);
        float var = Q * (1.0f / DMODEL) - mu * mu;
        s_mu = mu;
        s_r  = rsqrtf(var + 1e-5f);
    }
    __syncthreads();
    float mu = s_mu, r = s_r;
    float4 w4 = ((const float4*)w)[tid];
    float4 b4 = ((const float4*)b)[tid];
    float4 o4;
    o4.x = (v.x - mu) * r * w4.x + b4.x;
    o4.y = (v.y - mu) * r * w4.y + b4.y;
    o4.z = (v.z - mu) * r * w4.z + b4.z;
    o4.w = (v.w - mu) * r * w4.w + b4.w;
    ((float4*)(out + (size_t)row * DMODEL))[tid] = o4;
}

// ---------------------------------------------------------------------------
// tf32 mma.sync GEMM: C[M,N] = A[M,K] @ B[K,N] + bias, epilogue modes:
//   0: none   1: relu(v)+res   2: gelu(v)   3: v+res
// CTA 128x128, 256 thr, 8 warps (2m x 4n -> 64x32 warp tile), BK=32,
// double-buffered smem, pad-36 rows, m16n8k8.tf32 fragments.
// ---------------------------------------------------------------------------
#define GPAD 36
#define GTILE (128 * GPAD)              // floats per (A or B) tile
#define GBUF  (2 * GTILE)               // floats per stage buffer (A+B)
#define GEMM_SMEM_BYTES (2 * GBUF * 4)  // 73728 B

__global__ __launch_bounds__(256) void tgemm_kernel(
    const float* __restrict__ A, const float* __restrict__ B,
    const float* __restrict__ bias, const float* __restrict__ res,
    float* __restrict__ C, int M, int N, int K, int mode)
{
    extern __shared__ float sm[];

    int tid  = threadIdx.x;
    int lane = tid & 31;
    int wid  = tid >> 5;
    int wm   = wid >> 2;        // 0..1  (m)
    int wn   = wid & 3;         // 0..3  (n)
    int lr   = lane >> 2;       // 0..7
    int lc   = lane & 3;        // 0..3

    int bn = blockIdx.x * 128;
    int bm = blockIdx.y * 128;

    // global load indices
    int ar  = tid >> 1;               // A row (2 float4 per 32-col row; 256thr->... )
    // A tile: 128 rows x 32 cols = 1024 float4; thread does 4: idx = tid + t*256
    // B tile: 32 rows x 128 cols = 1024 float4

    float acc[4][4][4];
    #pragma unroll
    for (int i = 0; i < 4; i++)
        #pragma unroll
        for (int j = 0; j < 4; j++)
            #pragma unroll
            for (int q = 0; q < 4; q++) acc[i][j][q] = 0.f;

    float4 pa[4], pb[4];

    int NS = K >> 5;

    // ---- load stage 0 ----
    #pragma unroll
    for (int t = 0; t < 4; t++) {
        int idx = tid + t * 256;
        int r = idx >> 3, c4 = idx & 7;
        pa[t] = *(const float4*)(A + (size_t)(bm + r) * K + c4 * 4);
        int rb = idx >> 5, cb4 = idx & 31;
        pb[t] = *(const float4*)(B + (size_t)rb * N + bn + cb4 * 4);
    }
    {
        float* As = sm;
        float* Bs = sm + GTILE;
        #pragma unroll
        for (int t = 0; t < 4; t++) {
            int idx = tid + t * 256;
            int r = idx >> 3, c4 = idx & 7;
            uint32_t* dst = (uint32_t*)(As + r * GPAD + c4 * 4);
            dst[0] = f2tf32(pa[t].x); dst[1] = f2tf32(pa[t].y);
            dst[2] = f2tf32(pa[t].z); dst[3] = f2tf32(pa[t].w);
            int rb = idx >> 5, cb4 = idx & 31;
            uint32_t* bs = (uint32_t*)Bs;
            bs[(cb4 * 4 + 0) * GPAD + rb] = f2tf32(pb[t].x);
            bs[(cb4 * 4 + 1) * GPAD + rb] = f2tf32(pb[t].y);
            bs[(cb4 * 4 + 2) * GPAD + rb] = f2tf32(pb[t].z);
            bs[(cb4 * 4 + 3) * GPAD + rb] = f2tf32(pb[t].w);
        }
    }
    __syncthreads();

    for (int s = 0; s < NS; s++) {
        int k0n = (s + 1) * 32;
        if (s + 1 < NS) {
            #pragma unroll
            for (int t = 0; t < 4; t++) {
                int idx = tid + t * 256;
                int r = idx >> 3, c4 = idx & 7;
                pa[t] = *(const float4*)(A + (size_t)(bm + r) * K + k0n + c4 * 4);
                int rb = idx >> 5, cb4 = idx & 31;
                pb[t] = *(const float4*)(B + (size_t)(k0n + rb) * N + bn + cb4 * 4);
            }
        }

        const uint32_t* As = (const uint32_t*)(sm + (s & 1) * GBUF);
        const uint32_t* Bs = As + GTILE;

        #pragma unroll
        for (int kk = 0; kk < 4; kk++) {
            uint32_t af[4][4], bf[4][2];
            #pragma unroll
            for (int mt = 0; mt < 4; mt++) {
                int base = (wm * 64 + mt * 16 + lr) * GPAD + kk * 8 + lc;
                af[mt][0] = As[base];
                af[mt][1] = As[base + 8 * GPAD];
                af[mt][2] = As[base + 4];
                af[mt][3] = As[base + 8 * GPAD + 4];
            }
            #pragma unroll
            for (int nt = 0; nt < 4; nt++) {
                int base = (wn * 32 + nt * 8 + lr) * GPAD + kk * 8 + lc;
                bf[nt][0] = Bs[base];
                bf[nt][1] = Bs[base + 4];
            }
            #pragma unroll
            for (int mt = 0; mt < 4; mt++)
                #pragma unroll
                for (int nt = 0; nt < 4; nt++) {
                    asm volatile(
                        "mma.sync.aligned.m16n8k8.row.col.f32.tf32.tf32.f32 "
                        "{%0,%1,%2,%3}, {%4,%5,%6,%7}, {%8,%9}, {%0,%1,%2,%3};"
                        : "+f"(acc[mt][nt][0]), "+f"(acc[mt][nt][1]),
                          "+f"(acc[mt][nt][2]), "+f"(acc[mt][nt][3])
                        : "r"(af[mt][0]), "r"(af[mt][1]), "r"(af[mt][2]), "r"(af[mt][3]),
                          "r"(bf[nt][0]), "r"(bf[nt][1]));
                }
        }

        if (s + 1 < NS) {
            float* Asn = sm + ((s + 1) & 1) * GBUF;
            float* Bsn = Asn + GTILE;
            #pragma unroll
            for (int t = 0; t < 4; t++) {
                int idx = tid + t * 256;
                int r = idx >> 3, c4 = idx & 7;
                uint32_t* dst = (uint32_t*)(Asn + r * GPAD + c4 * 4);
                dst[0] = f2tf32(pa[t].x); dst[1] = f2tf32(pa[t].y);
                dst[2] = f2tf32(pa[t].z); dst[3] = f2tf32(pa[t].w);
                int rb = idx >> 5, cb4 = idx & 31;
                uint32_t* bs = (uint32_t*)Bsn;
                bs[(cb4 * 4 + 0) * GPAD + rb] = f2tf32(pb[t].x);
                bs[(cb4 * 4 + 1) * GPAD + rb] = f2tf32(pb[t].y);
                bs[(cb4 * 4 + 2) * GPAD + rb] = f2tf32(pb[t].z);
                bs[(cb4 * 4 + 3) * GPAD + rb] = f2tf32(pb[t].w);
            }
        }
        __syncthreads();
    }

    // ---- epilogue ----
    #pragma unroll
    for (int mt = 0; mt < 4; mt++) {
        #pragma unroll
        for (int half = 0; half < 2; half++) {
            int row = bm + wm * 64 + mt * 16 + lr + half * 8;
            float* cr = C + (size_t)row * N;
            const float* rr = (mode == 1 || mode == 3) ? (res + (size_t)row * N) : nullptr;
            #pragma unroll
            for (int nt = 0; nt < 4; nt++) {
                int col = bn + wn * 32 + nt * 8 + lc * 2;
                float v0 = acc[mt][nt][half * 2 + 0] + bias[col];
                float v1 = acc[mt][nt][half * 2 + 1] + bias[col + 1];
                if (mode == 1) {
                    v0 = fmaxf(v0, 0.f) + rr[col];
                    v1 = fmaxf(v1, 0.f) + rr[col + 1];
                } else if (mode == 2) {
                    v0 = 0.5f * v0 * (1.f + erff(v0 * 0.70710678118654752f));
                    v1 = 0.5f * v1 * (1.f + erff(v1 * 0.70710678118654752f));
                } else if (mode == 3) {
                    v0 += rr[col];
                    v1 += rr[col + 1];
                }
                float2 o; o.x = v0; o.y = v1;
                *(float2*)(cr + col) = o;
            }
        }
    }
}

// ---------------------------------------------------------------------------
// Flash attention (fp32): grid (S/64, B*H), 256 threads (8 warps).
// ---------------------------------------------------------------------------
#define ATTN_SMEM_FLOATS (64*64 + 64*68 + 64*68)

__global__ __launch_bounds__(256) void attn_kernel(
    const float* __restrict__ Qg, const float* __restrict__ Kg,
    const float* __restrict__ Vg, float* __restrict__ Og)
{
    extern __shared__ float sm[];
    float* sQ  = sm;
    float* sK  = sm + 64 * 64;
    float* sVt = sK + 64 * 68;

    int bh = blockIdx.y;
    int b  = bh >> 4;
    int h  = bh & 15;
    int q0 = blockIdx.x * 64;

    size_t base = (size_t)b * 1024 * DMODEL + (size_t)h * DKH;
    const float* Qb = Qg + base;
    const float* Kb = Kg + base;
    const float* Vb = Vg + base;
    float*       Ob = Og + base;

    int tid  = threadIdx.x;
    int lane = tid & 31;
    int w    = tid >> 5;
    int r0   = w * 8;

    int rr = tid >> 4;
    int cc = (tid & 15) * 4;

    #pragma unroll
    for (int it = 0; it < 4; it++) {
        int row = rr + it * 16;
        float4 v = *(const float4*)(Qb + (size_t)(q0 + row) * DMODEL + cc);
        v.x *= 0.125f; v.y *= 0.125f; v.z *= 0.125f; v.w *= 0.125f;
        *(float4*)(sQ + row * 64 + cc) = v;
    }

    float m[8], l[8], o0[8], o1[8];
    #pragma unroll
    for (int r = 0; r < 8; r++) { m[r] = -1e30f; l[r] = 0.f; o0[r] = 0.f; o1[r] = 0.f; }

    for (int kt = 0; kt < 16; kt++) {
        __syncthreads();
        #pragma unroll
        for (int it = 0; it < 4; it++) {
            int j = rr + it * 16;
            float4 kv = *(const float4*)(Kb + (size_t)(kt * 64 + j) * DMODEL + cc);
            *(float4*)(sK + j * 68 + cc) = kv;
            float4 vv = *(const float4*)(Vb + (size_t)(kt * 64 + j) * DMODEL + cc);
            sVt[(cc + 0) * 68 + j] = vv.x;
            sVt[(cc + 1) * 68 + j] = vv.y;
            sVt[(cc + 2) * 68 + j] = vv.z;
            sVt[(cc + 3) * 68 + j] = vv.w;
        }
        __syncthreads();

        float s0[8], s1[8];
        #pragma unroll
        for (int r = 0; r < 8; r++) { s0[r] = 0.f; s1[r] = 0.f; }
        #pragma unroll
        for (int d = 0; d < 64; d += 4) {
            float4 k0 = *(const float4*)(sK + lane * 68 + d);
            float4 k1 = *(const float4*)(sK + (lane + 32) * 68 + d);
            #pragma unroll
            for (int r = 0; r < 8; r++) {
                float4 q4 = *(const float4*)(sQ + (r0 + r) * 64 + d);
                s0[r] += q4.x * k0.x + q4.y * k0.y + q4.z * k0.z + q4.w * k0.w;
                s1[r] += q4.x * k1.x + q4.y * k1.y + q4.z * k1.z + q4.w * k1.w;
            }
        }

        float p0[8], p1[8];
        #pragma unroll
        for (int r = 0; r < 8; r++) {
            float mx = fmaxf(s0[r], s1[r]);
            #pragma unroll
            for (int o = 16; o; o >>= 1)
                mx = fmaxf(mx, __shfl_xor_sync(0xffffffffu, mx, o));
            float mn = fmaxf(m[r], mx);
            float a  = __expf(m[r] - mn);
            p0[r] = __expf(s0[r] - mn);
            p1[r] = __expf(s1[r] - mn);
            float ps = p0[r] + p1[r];
            #pragma unroll
            for (int o = 16; o; o >>= 1)
                ps += __shfl_xor_sync(0xffffffffu, ps, o);
            l[r] = l[r] * a + ps;
            o0[r] *= a;
            o1[r] *= a;
            m[r] = mn;
        }

        __syncthreads();
        #pragma unroll
        for (int r = 0; r < 8; r++) {
            sK[(r0 + r) * 68 + lane]      = p0[r];
            sK[(r0 + r) * 68 + lane + 32] = p1[r];
        }
        __syncthreads();

        #pragma unroll
        for (int j = 0; j < 64; j += 4) {
            float4 v0 = *(const float4*)(sVt + lane * 68 + j);
            float4 v1 = *(const float4*)(sVt + (lane + 32) * 68 + j);
            #pragma unroll
            for (int r = 0; r < 8; r++) {
                float4 p4 = *(const float4*)(sK + (r0 + r) * 68 + j);
                o0[r] += p4.x * v0.x + p4.y * v0.y + p4.z * v0.z + p4.w * v0.w;
                o1[r] += p4.x * v1.x + p4.y * v1.y + p4.z * v1.z + p4.w * v1.w;
            }
        }
    }

    #pragma unroll
    for (int r = 0; r < 8; r++) {
        float inv = 1.f / l[r];
        size_t off = (size_t)(q0 + r0 + r) * DMODEL;
        Ob[off + lane]      = o0[r] * inv;
        Ob[off + lane + 32] = o1[r] * inv;
    }
}

// ---------------------------------------------------------------------------
// Host launcher
// ---------------------------------------------------------------------------
extern "C" void kernel_launch(void* const* d_in, const int* in_sizes, int n_in,
                              void* d_out, int out_size)
{
    const float* x     = (const float*)d_in[0];
    const float* ln1_w = (const float*)d_in[1];
    const float* ln1_b = (const float*)d_in[2];
    const float* wq    = (const float*)d_in[3];
    const float* bq    = (const float*)d_in[4];
    const float* wk    = (const float*)d_in[5];
    const float* bk    = (const float*)d_in[6];
    const float* wv    = (const float*)d_in[7];
    const float* bv    = (const float*)d_in[8];
    const float* wo    = (const float*)d_in[9];
    const float* bo    = (const float*)d_in[10];
    const float* ln2_w = (const float*)d_in[11];
    const float* ln2_b = (const float*)d_in[12];
    const float* w1    = (const float*)d_in[13];
    const float* b1    = (const float*)d_in[14];
    const float* w2    = (const float*)d_in[15];
    const float* b2    = (const float*)d_in[16];

    float *p_h, *p_q, *p_k, *p_v, *p_ctx, *p_out1, *p_h2, *p_ff;
    cudaGetSymbolAddress((void**)&p_h,    g_h);
    cudaGetSymbolAddress((void**)&p_q,    g_q);
    cudaGetSymbolAddress((void**)&p_k,    g_k);
    cudaGetSymbolAddress((void**)&p_v,    g_v);
    cudaGetSymbolAddress((void**)&p_ctx,  g_ctx);
    cudaGetSymbolAddress((void**)&p_out1, g_out1);
    cudaGetSymbolAddress((void**)&p_h2,   g_h2);
    cudaGetSymbolAddress((void**)&p_ff,   g_ff);

    cudaFuncSetAttribute(attn_kernel, cudaFuncAttributeMaxDynamicSharedMemorySize,
                         ATTN_SMEM_FLOATS * 4);
    cudaFuncSetAttribute(tgemm_kernel, cudaFuncAttributeMaxDynamicSharedMemorySize,
                         GEMM_SMEM_BYTES);

    // 1) ln1
    ln_kernel<<<TOK, 256>>>(x, ln1_w, ln1_b, p_h);
    // 2) QKV projections (tf32 mma.sync)
    tgemm_kernel<<<dim3(8, 64), 256, GEMM_SMEM_BYTES>>>(p_h, wq, bq, nullptr, p_q, TOK, DMODEL, DMODEL, 0);
    tgemm_kernel<<<dim3(8, 64), 256, GEMM_SMEM_BYTES>>>(p_h, wk, bk, nullptr, p_k, TOK, DMODEL, DMODEL, 0);
    tgemm_kernel<<<dim3(8, 64), 256, GEMM_SMEM_BYTES>>>(p_h, wv, bv, nullptr, p_v, TOK, DMODEL, DMODEL, 0);
    // 3) attention (fp32)
    attn_kernel<<<dim3(16, 128), 256, ATTN_SMEM_FLOATS * 4>>>(p_q, p_k, p_v, p_ctx);
    // 4) out proj + relu + residual(x)
    tgemm_kernel<<<dim3(8, 64), 256, GEMM_SMEM_BYTES>>>(p_ctx, wo, bo, x, p_out1, TOK, DMODEL, DMODEL, 1);
    // 5) ln2
    ln_kernel<<<TOK, 256>>>(p_out1, ln2_w, ln2_b, p_h2);
    // 6) MLP up + gelu
    tgemm_kernel<<<dim3(32, 64), 256, GEMM_SMEM_BYTES>>>(p_h2, w1, b1, nullptr, p_ff, TOK, DMLP, DMODEL, 2);
    // 7) MLP down + residual(out1) -> d_out
    tgemm_kernel<<<dim3(8, 64), 256, GEMM_SMEM_BYTES>>>(p_ff, w2, b2, p_out1, (float*)d_out, TOK, DMODEL, DMLP, 3);
}

// round 5
// speedup vs baseline: 2.3416x; 1.6885x over previous
#include <cuda_runtime.h>
#include <cuda_bf16.h>
#include <math.h>
#include <stdint.h>

// ---------------------------------------------------------------------------
// Problem constants: B=8, S=1024, D=1024, H=16, DK=64, MLP=4096, tokens=8192
// ---------------------------------------------------------------------------
#define TOK    8192
#define DMODEL 1024
#define NHEAD  16
#define DKH    64
#define DMLP   4096

// ---------------------------------------------------------------------------
// Scratch (device globals; no allocation allowed)
// ---------------------------------------------------------------------------
__device__ float g_h   [TOK * DMODEL];
__device__ float g_q   [TOK * DMODEL];
__device__ float g_k   [TOK * DMODEL];
__device__ float g_v   [TOK * DMODEL];
__device__ float g_ctx [TOK * DMODEL];
__device__ float g_out1[TOK * DMODEL];
__device__ float g_h2  [TOK * DMODEL];
__device__ float g_ff  [TOK * DMLP];
__device__ float g_wbuf[12 * 1024 * 1024];   // rounded weights: wq,wk,wv,wo,w1,w2

__device__ __forceinline__ uint32_t f2tf32(float x) {
    uint32_t r; asm("cvt.rna.tf32.f32 %0, %1;" : "=r"(r) : "f"(x)); return r;
}
__device__ __forceinline__ float rtf(float x) { return __uint_as_float(f2tf32(x)); }
__device__ __forceinline__ uint32_t s2u(const void* p) {
    uint32_t a;
    asm("{ .reg .u64 t; cvta.to.shared.u64 t, %1; cvt.u32.u64 %0, t; }" : "=r"(a) : "l"(p));
    return a;
}
__device__ __forceinline__ void cpa16(uint32_t dst, const void* src) {
    asm volatile("cp.async.cg.shared.global [%0], [%1], 16;" :: "r"(dst), "l"(src) : "memory");
}

// ---------------------------------------------------------------------------
// Weight pre-round: RNA-round to tf32 grid (float4 copy)
// ---------------------------------------------------------------------------
__global__ __launch_bounds__(256) void round_kernel(
    const float* __restrict__ src, float* __restrict__ dst, int n4)
{
    int i = blockIdx.x * 256 + threadIdx.x;
    if (i < n4) {
        float4 v = ((const float4*)src)[i];
        v.x = rtf(v.x); v.y = rtf(v.y); v.z = rtf(v.z); v.w = rtf(v.w);
        ((float4*)dst)[i] = v;
    }
}

// ---------------------------------------------------------------------------
// LayerNorm: one block per row (D=1024), 256 threads, float4.
// Output is RNA-rounded to tf32 grid (consumed only as GEMM A operand).
// ---------------------------------------------------------------------------
__global__ __launch_bounds__(256) void ln_kernel(
    const float* __restrict__ x, const float* __restrict__ w,
    const float* __restrict__ b, float* __restrict__ out)
{
    int row = blockIdx.x;
    int tid = threadIdx.x;
    const float4* xr = (const float4*)(x + (size_t)row * DMODEL);
    float4 v = xr[tid];
    float s  = v.x + v.y + v.z + v.w;
    float sq = v.x*v.x + v.y*v.y + v.z*v.z + v.w*v.w;
    #pragma unroll
    for (int o = 16; o; o >>= 1) {
        s  += __shfl_xor_sync(0xffffffffu, s,  o);
        sq += __shfl_xor_sync(0xffffffffu, sq, o);
    }
    __shared__ float ss[8], ssq[8];
    __shared__ float s_mu, s_r;
    if ((tid & 31) == 0) { ss[tid >> 5] = s; ssq[tid >> 5] = sq; }
    __syncthreads();
    if (tid == 0) {
        float S = 0.f, Q = 0.f;
        #pragma unroll
        for (int i = 0; i < 8; i++) { S += ss[i]; Q += ssq[i]; }
        float mu  = S * (1.0f / DMODEL);
        float var = Q * (1.0f / DMODEL) - mu * mu;
        s_mu = mu;
        s_r  = rsqrtf(var + 1e-5f);
    }
    __syncthreads();
    float mu = s_mu, r = s_r;
    float4 w4 = ((const float4*)w)[tid];
    float4 b4 = ((const float4*)b)[tid];
    float4 o4;
    o4.x = rtf((v.x - mu) * r * w4.x + b4.x);
    o4.y = rtf((v.y - mu) * r * w4.y + b4.y);
    o4.z = rtf((v.z - mu) * r * w4.z + b4.z);
    o4.w = rtf((v.w - mu) * r * w4.w + b4.w);
    ((float4*)(out + (size_t)row * DMODEL))[tid] = o4;
}

// ---------------------------------------------------------------------------
// tf32 mma.sync GEMM v2: cp.async double-buffer + ldmatrix A frags.
// C[M,N] = A[M,K]@B[K,N] + bias; modes: 0 none, 1 relu+res, 2 gelu(->tf32), 3 +res
// CTA 128x128, 256 thr, warps 2m x 4n (64x32 tiles), BK=32.
// smem/stage: A[128][36] + B[32][136]  (both conflict-free)
// ---------------------------------------------------------------------------
#define APITCH 36
#define BPITCH 136
#define ASTG (128 * APITCH)
#define BSTG (32 * BPITCH)
#define STG  (ASTG + BSTG)
#define GEMM_SMEM_BYTES (2 * STG * 4)

__global__ __launch_bounds__(256, 2) void tgemm_kernel(
    const float* __restrict__ A, const float* __restrict__ B,
    const float* __restrict__ bias, const float* __restrict__ res,
    float* __restrict__ C, int M, int N, int K, int mode)
{
    extern __shared__ float sm[];
    uint32_t smb = s2u(sm);

    int tid  = threadIdx.x;
    int lane = tid & 31;
    int wid  = tid >> 5;
    int wm   = wid >> 2;
    int wn   = wid & 3;
    int lr   = lane >> 2;
    int lc   = lane & 3;

    int bn = blockIdx.x * 128;
    int bm = blockIdx.y * 128;

    // cp.async chunk coords (per thread, 4 chunks A + 4 chunks B per stage)
    int arA[4], acA[4], krB[4], cnB[4];
    #pragma unroll
    for (int t = 0; t < 4; t++) {
        int idx = tid + t * 256;
        arA[t] = idx >> 3;  acA[t] = idx & 7;     // A: row, 16B-chunk (k/4)
        krB[t] = idx >> 5;  cnB[t] = idx & 31;    // B: k-row, 16B-chunk (n/4)
    }

    // ldmatrix lane address pieces for A
    int mat = lane >> 3;
    int mrow = (lane & 7) + ((mat & 1) << 3);     // row within 16
    int makk = (mat >> 1) << 2;                    // 0 or 4
    uint32_t aoff = (uint32_t)(((wm * 64 + mrow) * APITCH + makk) * 4);

    float acc[4][4][4];
    #pragma unroll
    for (int i = 0; i < 4; i++)
        #pragma unroll
        for (int j = 0; j < 4; j++)
            #pragma unroll
            for (int q = 0; q < 4; q++) acc[i][j][q] = 0.f;

    int NS = K >> 5;

    // ---- issue copies for stage 0 and 1 ----
    #pragma unroll
    for (int st = 0; st < 2; st++) {
        uint32_t Ab = smb + (uint32_t)st * STG * 4;
        uint32_t Bb = Ab + ASTG * 4;
        int k0 = st * 32;
        #pragma unroll
        for (int t = 0; t < 4; t++) {
            cpa16(Ab + (uint32_t)(arA[t] * APITCH + acA[t] * 4) * 4,
                  A + (size_t)(bm + arA[t]) * K + k0 + acA[t] * 4);
            cpa16(Bb + (uint32_t)(krB[t] * BPITCH + cnB[t] * 4) * 4,
                  B + (size_t)(k0 + krB[t]) * N + bn + cnB[t] * 4);
        }
        asm volatile("cp.async.commit_group;" ::: "memory");
    }
    asm volatile("cp.async.wait_group 1;" ::: "memory");
    __syncthreads();

    for (int s = 0; s < NS; s++) {
        uint32_t Ab = smb + (uint32_t)(s & 1) * STG * 4;
        const uint32_t* Bs = (const uint32_t*)(sm + (size_t)(s & 1) * STG + ASTG);

        #pragma unroll
        for (int kk = 0; kk < 4; kk++) {
            uint32_t af[4][4];
            #pragma unroll
            for (int mt = 0; mt < 4; mt++) {
                uint32_t addr = Ab + aoff + (uint32_t)((mt * 16 * APITCH + kk * 8) * 4);
                asm volatile(
                    "ldmatrix.sync.aligned.m8n8.x4.shared.b16 {%0,%1,%2,%3}, [%4];"
                    : "=r"(af[mt][0]), "=r"(af[mt][1]), "=r"(af[mt][2]), "=r"(af[mt][3])
                    : "r"(addr));
            }
            uint32_t bf[4][2];
            int krow0 = (kk * 8 + lc) * BPITCH + wn * 32 + lr;
            #pragma unroll
            for (int nt = 0; nt < 4; nt++) {
                bf[nt][0] = Bs[krow0 + nt * 8];
                bf[nt][1] = Bs[krow0 + 4 * BPITCH + nt * 8];
            }
            #pragma unroll
            for (int mt = 0; mt < 4; mt++)
                #pragma unroll
                for (int nt = 0; nt < 4; nt++) {
                    asm volatile(
                        "mma.sync.aligned.m16n8k8.row.col.f32.tf32.tf32.f32 "
                        "{%0,%1,%2,%3}, {%4,%5,%6,%7}, {%8,%9}, {%0,%1,%2,%3};"
                        : "+f"(acc[mt][nt][0]), "+f"(acc[mt][nt][1]),
                          "+f"(acc[mt][nt][2]), "+f"(acc[mt][nt][3])
                        : "r"(af[mt][0]), "r"(af[mt][1]), "r"(af[mt][2]), "r"(af[mt][3]),
                          "r"(bf[nt][0]), "r"(bf[nt][1]));
                }
        }

        if (s + 1 == NS) break;
        __syncthreads();
        if (s + 2 < NS) {
            uint32_t Ab2 = smb + (uint32_t)(s & 1) * STG * 4;
            uint32_t Bb2 = Ab2 + ASTG * 4;
            int k0 = (s + 2) * 32;
            #pragma unroll
            for (int t = 0; t < 4; t++) {
                cpa16(Ab2 + (uint32_t)(arA[t] * APITCH + acA[t] * 4) * 4,
                      A + (size_t)(bm + arA[t]) * K + k0 + acA[t] * 4);
                cpa16(Bb2 + (uint32_t)(krB[t] * BPITCH + cnB[t] * 4) * 4,
                      B + (size_t)(k0 + krB[t]) * N + bn + cnB[t] * 4);
            }
            asm volatile("cp.async.commit_group;" ::: "memory");
            asm volatile("cp.async.wait_group 1;" ::: "memory");
        } else {
            asm volatile("cp.async.wait_group 0;" ::: "memory");
        }
        __syncthreads();
    }

    // ---- epilogue ----
    #pragma unroll
    for (int mt = 0; mt < 4; mt++) {
        #pragma unroll
        for (int half = 0; half < 2; half++) {
            int row = bm + wm * 64 + mt * 16 + lr + half * 8;
            float* cr = C + (size_t)row * N;
            const float* rr = (mode == 1 || mode == 3) ? (res + (size_t)row * N) : nullptr;
            #pragma unroll
            for (int nt = 0; nt < 4; nt++) {
                int col = bn + wn * 32 + nt * 8 + lc * 2;
                float v0 = acc[mt][nt][half * 2 + 0] + bias[col];
                float v1 = acc[mt][nt][half * 2 + 1] + bias[col + 1];
                if (mode == 1) {
                    v0 = fmaxf(v0, 0.f) + rr[col];
                    v1 = fmaxf(v1, 0.f) + rr[col + 1];
                } else if (mode == 2) {
                    v0 = rtf(0.5f * v0 * (1.f + erff(v0 * 0.70710678118654752f)));
                    v1 = rtf(0.5f * v1 * (1.f + erff(v1 * 0.70710678118654752f)));
                } else if (mode == 3) {
                    v0 += rr[col];
                    v1 += rr[col + 1];
                }
                float2 o; o.x = v0; o.y = v1;
                *(float2*)(cr + col) = o;
            }
        }
    }
}

// ---------------------------------------------------------------------------
// Flash attention (fp32): grid (S/64, B*H), 256 threads (8 warps).
// Output rounded to tf32 grid (consumed only as GEMM A operand of wo-proj).
// ---------------------------------------------------------------------------
#define ATTN_SMEM_FLOATS (64*64 + 64*68 + 64*68)

__global__ __launch_bounds__(256) void attn_kernel(
    const float* __restrict__ Qg, const float* __restrict__ Kg,
    const float* __restrict__ Vg, float* __restrict__ Og)
{
    extern __shared__ float sm[];
    float* sQ  = sm;
    float* sK  = sm + 64 * 64;
    float* sVt = sK + 64 * 68;

    int bh = blockIdx.y;
    int b  = bh >> 4;
    int h  = bh & 15;
    int q0 = blockIdx.x * 64;

    size_t base = (size_t)b * 1024 * DMODEL + (size_t)h * DKH;
    const float* Qb = Qg + base;
    const float* Kb = Kg + base;
    const float* Vb = Vg + base;
    float*       Ob = Og + base;

    int tid  = threadIdx.x;
    int lane = tid & 31;
    int w    = tid >> 5;
    int r0   = w * 8;

    int rr = tid >> 4;
    int cc = (tid & 15) * 4;

    #pragma unroll
    for (int it = 0; it < 4; it++) {
        int row = rr + it * 16;
        float4 v = *(const float4*)(Qb + (size_t)(q0 + row) * DMODEL + cc);
        v.x *= 0.125f; v.y *= 0.125f; v.z *= 0.125f; v.w *= 0.125f;
        *(float4*)(sQ + row * 64 + cc) = v;
    }

    float m[8], l[8], o0[8], o1[8];
    #pragma unroll
    for (int r = 0; r < 8; r++) { m[r] = -1e30f; l[r] = 0.f; o0[r] = 0.f; o1[r] = 0.f; }

    for (int kt = 0; kt < 16; kt++) {
        __syncthreads();
        #pragma unroll
        for (int it = 0; it < 4; it++) {
            int j = rr + it * 16;
            float4 kv = *(const float4*)(Kb + (size_t)(kt * 64 + j) * DMODEL + cc);
            *(float4*)(sK + j * 68 + cc) = kv;
            float4 vv = *(const float4*)(Vb + (size_t)(kt * 64 + j) * DMODEL + cc);
            sVt[(cc + 0) * 68 + j] = vv.x;
            sVt[(cc + 1) * 68 + j] = vv.y;
            sVt[(cc + 2) * 68 + j] = vv.z;
            sVt[(cc + 3) * 68 + j] = vv.w;
        }
        __syncthreads();

        float s0[8], s1[8];
        #pragma unroll
        for (int r = 0; r < 8; r++) { s0[r] = 0.f; s1[r] = 0.f; }
        #pragma unroll
        for (int d = 0; d < 64; d += 4) {
            float4 k0 = *(const float4*)(sK + lane * 68 + d);
            float4 k1 = *(const float4*)(sK + (lane + 32) * 68 + d);
            #pragma unroll
            for (int r = 0; r < 8; r++) {
                float4 q4 = *(const float4*)(sQ + (r0 + r) * 64 + d);
                s0[r] += q4.x * k0.x + q4.y * k0.y + q4.z * k0.z + q4.w * k0.w;
                s1[r] += q4.x * k1.x + q4.y * k1.y + q4.z * k1.z + q4.w * k1.w;
            }
        }

        float p0[8], p1[8];
        #pragma unroll
        for (int r = 0; r < 8; r++) {
            float mx = fmaxf(s0[r], s1[r]);
            #pragma unroll
            for (int o = 16; o; o >>= 1)
                mx = fmaxf(mx, __shfl_xor_sync(0xffffffffu, mx, o));
            float mn = fmaxf(m[r], mx);
            float a  = __expf(m[r] - mn);
            p0[r] = __expf(s0[r] - mn);
            p1[r] = __expf(s1[r] - mn);
            float ps = p0[r] + p1[r];
            #pragma unroll
            for (int o = 16; o; o >>= 1)
                ps += __shfl_xor_sync(0xffffffffu, ps, o);
            l[r] = l[r] * a + ps;
            o0[r] *= a;
            o1[r] *= a;
            m[r] = mn;
        }

        __syncthreads();
        #pragma unroll
        for (int r = 0; r < 8; r++) {
            sK[(r0 + r) * 68 + lane]      = p0[r];
            sK[(r0 + r) * 68 + lane + 32] = p1[r];
        }
        __syncthreads();

        #pragma unroll
        for (int j = 0; j < 64; j += 4) {
            float4 v0 = *(const float4*)(sVt + lane * 68 + j);
            float4 v1 = *(const float4*)(sVt + (lane + 32) * 68 + j);
            #pragma unroll
            for (int r = 0; r < 8; r++) {
                float4 p4 = *(const float4*)(sK + (r0 + r) * 68 + j);
                o0[r] += p4.x * v0.x + p4.y * v0.y + p4.z * v0.z + p4.w * v0.w;
                o1[r] += p4.x * v1.x + p4.y * v1.y + p4.z * v1.z + p4.w * v1.w;
            }
        }
    }

    #pragma unroll
    for (int r = 0; r < 8; r++) {
        float inv = 1.f / l[r];
        size_t off = (size_t)(q0 + r0 + r) * DMODEL;
        Ob[off + lane]      = rtf(o0[r] * inv);
        Ob[off + lane + 32] = rtf(o1[r] * inv);
    }
}

// ---------------------------------------------------------------------------
// Host launcher
// ---------------------------------------------------------------------------
extern "C" void kernel_launch(void* const* d_in, const int* in_sizes, int n_in,
                              void* d_out, int out_size)
{
    const float* x     = (const float*)d_in[0];
    const float* ln1_w = (const float*)d_in[1];
    const float* ln1_b = (const float*)d_in[2];
    const float* wq    = (const float*)d_in[3];
    const float* bq    = (const float*)d_in[4];
    const float* wk    = (const float*)d_in[5];
    const float* bk    = (const float*)d_in[6];
    const float* wv    = (const float*)d_in[7];
    const float* bv    = (const float*)d_in[8];
    const float* wo    = (const float*)d_in[9];
    const float* bo    = (const float*)d_in[10];
    const float* ln2_w = (const float*)d_in[11];
    const float* ln2_b = (const float*)d_in[12];
    const float* w1    = (const float*)d_in[13];
    const float* b1    = (const float*)d_in[14];
    const float* w2    = (const float*)d_in[15];
    const float* b2    = (const float*)d_in[16];

    float *p_h, *p_q, *p_k, *p_v, *p_ctx, *p_out1, *p_h2, *p_ff, *p_w;
    cudaGetSymbolAddress((void**)&p_h,    g_h);
    cudaGetSymbolAddress((void**)&p_q,    g_q);
    cudaGetSymbolAddress((void**)&p_k,    g_k);
    cudaGetSymbolAddress((void**)&p_v,    g_v);
    cudaGetSymbolAddress((void**)&p_ctx,  g_ctx);
    cudaGetSymbolAddress((void**)&p_out1, g_out1);
    cudaGetSymbolAddress((void**)&p_h2,   g_h2);
    cudaGetSymbolAddress((void**)&p_ff,   g_ff);
    cudaGetSymbolAddress((void**)&p_w,    g_wbuf);

    const int MB = 1024 * 1024;
    float* rwq = p_w;
    float* rwk = p_w + 1 * MB;
    float* rwv = p_w + 2 * MB;
    float* rwo = p_w + 3 * MB;
    float* rw1 = p_w + 4 * MB;
    float* rw2 = p_w + 8 * MB;

    cudaFuncSetAttribute(attn_kernel, cudaFuncAttributeMaxDynamicSharedMemorySize,
                         ATTN_SMEM_FLOATS * 4);
    cudaFuncSetAttribute(tgemm_kernel, cudaFuncAttributeMaxDynamicSharedMemorySize,
                         GEMM_SMEM_BYTES);

    // 0) weight pre-round (~12us)
    round_kernel<<<(MB / 4 + 255) / 256, 256>>>(wq, rwq, MB / 4);
    round_kernel<<<(MB / 4 + 255) / 256, 256>>>(wk, rwk, MB / 4);
    round_kernel<<<(MB / 4 + 255) / 256, 256>>>(wv, rwv, MB / 4);
    round_kernel<<<(MB / 4 + 255) / 256, 256>>>(wo, rwo, MB / 4);
    round_kernel<<<(4 * MB / 4 + 255) / 256, 256>>>(w1, rw1, 4 * MB / 4);
    round_kernel<<<(4 * MB / 4 + 255) / 256, 256>>>(w2, rw2, 4 * MB / 4);

    // 1) ln1 (tf32-rounded out)
    ln_kernel<<<TOK, 256>>>(x, ln1_w, ln1_b, p_h);
    // 2) QKV projections
    tgemm_kernel<<<dim3(8, 64), 256, GEMM_SMEM_BYTES>>>(p_h, rwq, bq, nullptr, p_q, TOK, DMODEL, DMODEL, 0);
    tgemm_kernel<<<dim3(8, 64), 256, GEMM_SMEM_BYTES>>>(p_h, rwk, bk, nullptr, p_k, TOK, DMODEL, DMODEL, 0);
    tgemm_kernel<<<dim3(8, 64), 256, GEMM_SMEM_BYTES>>>(p_h, rwv, bv, nullptr, p_v, TOK, DMODEL, DMODEL, 0);
    // 3) attention (fp32, tf32-rounded out)
    attn_kernel<<<dim3(16, 128), 256, ATTN_SMEM_FLOATS * 4>>>(p_q, p_k, p_v, p_ctx);
    // 4) out proj + relu + residual(x)
    tgemm_kernel<<<dim3(8, 64), 256, GEMM_SMEM_BYTES>>>(p_ctx, rwo, bo, x, p_out1, TOK, DMODEL, DMODEL, 1);
    // 5) ln2 (tf32-rounded out)
    ln_kernel<<<TOK, 256>>>(p_out1, ln2_w, ln2_b, p_h2);
    // 6) MLP up + gelu (tf32-rounded out)
    tgemm_kernel<<<dim3(32, 64), 256, GEMM_SMEM_BYTES>>>(p_h2, rw1, b1, nullptr, p_ff, TOK, DMLP, DMODEL, 2);
    // 7) MLP down + residual(out1) -> d_out
    tgemm_kernel<<<dim3(8, 64), 256, GEMM_SMEM_BYTES>>>(p_ff, rw2, b2, p_out1, (float*)d_out, TOK, DMODEL, DMLP, 3);
}

// round 6
// speedup vs baseline: 3.6760x; 1.5699x over previous
#include <cuda_runtime.h>
#include <cuda_bf16.h>
#include <math.h>
#include <stdint.h>

// ---------------------------------------------------------------------------
// Problem constants: B=8, S=1024, D=1024, H=16, DK=64, MLP=4096, tokens=8192
// ---------------------------------------------------------------------------
#define TOK    8192
#define DMODEL 1024
#define NHEAD  16
#define DKH    64
#define DMLP   4096

// ---------------------------------------------------------------------------
// Scratch (device globals; no allocation allowed)
// ---------------------------------------------------------------------------
__device__ float g_h   [TOK * DMODEL];
__device__ float g_qkv [TOK * 3 * DMODEL];
__device__ float g_ctx [TOK * DMODEL];
__device__ float g_out1[TOK * DMODEL];
__device__ float g_h2  [TOK * DMODEL];
__device__ float g_ff  [TOK * DMLP];
__device__ float g_wbuf[13 * 1024 * 1024];  // rwqkv(3M) rwo(1M) rw1(4M) rw2(4M) bqkv(3072)

__device__ __forceinline__ uint32_t f2tf32(float x) {
    uint32_t r; asm("cvt.rna.tf32.f32 %0, %1;" : "=r"(r) : "f"(x)); return r;
}
__device__ __forceinline__ float rtf(float x) { return __uint_as_float(f2tf32(x)); }
__device__ __forceinline__ uint32_t s2u(const void* p) {
    uint32_t a;
    asm("{ .reg .u64 t; cvta.to.shared.u64 t, %1; cvt.u32.u64 %0, t; }" : "=r"(a) : "l"(p));
    return a;
}
__device__ __forceinline__ void cpa16(uint32_t dst, const void* src) {
    asm volatile("cp.async.cg.shared.global [%0], [%1], 16;" :: "r"(dst), "l"(src) : "memory");
}

// ---------------------------------------------------------------------------
// Weight pre-round / pack kernels
// ---------------------------------------------------------------------------
__global__ __launch_bounds__(256) void round_kernel(
    const float* __restrict__ src, float* __restrict__ dst, int n4)
{
    int i = blockIdx.x * 256 + threadIdx.x;
    if (i < n4) {
        float4 v = ((const float4*)src)[i];
        v.x = rtf(v.x); v.y = rtf(v.y); v.z = rtf(v.z); v.w = rtf(v.w);
        ((float4*)dst)[i] = v;
    }
}
// pack a [1024,1024] weight into columns [off, off+1024) of a [1024,3072] buffer
__global__ __launch_bounds__(256) void packw_kernel(
    const float* __restrict__ src, float* __restrict__ dst, int off)
{
    int i = blockIdx.x * 256 + threadIdx.x;       // over 1024*256 float4
    int row = i >> 8, c4 = i & 255;
    float4 v = ((const float4*)src)[row * 256 + c4];
    v.x = rtf(v.x); v.y = rtf(v.y); v.z = rtf(v.z); v.w = rtf(v.w);
    ((float4*)(dst + (size_t)row * 3072 + off))[c4] = v;
}
__global__ __launch_bounds__(256) void packb_kernel(
    const float* __restrict__ bq, const float* __restrict__ bk,
    const float* __restrict__ bv, float* __restrict__ dst)
{
    int i = blockIdx.x * 256 + threadIdx.x;
    if (i < 3072)
        dst[i] = (i < 1024) ? bq[i] : (i < 2048) ? bk[i - 1024] : bv[i - 2048];
}

// ---------------------------------------------------------------------------
// LayerNorm: one block per row (D=1024), 256 threads, float4, tf32-rounded out
// ---------------------------------------------------------------------------
__global__ __launch_bounds__(256) void ln_kernel(
    const float* __restrict__ x, const float* __restrict__ w,
    const float* __restrict__ b, float* __restrict__ out)
{
    int row = blockIdx.x;
    int tid = threadIdx.x;
    const float4* xr = (const float4*)(x + (size_t)row * DMODEL);
    float4 v = xr[tid];
    float s  = v.x + v.y + v.z + v.w;
    float sq = v.x*v.x + v.y*v.y + v.z*v.z + v.w*v.w;
    #pragma unroll
    for (int o = 16; o; o >>= 1) {
        s  += __shfl_xor_sync(0xffffffffu, s,  o);
        sq += __shfl_xor_sync(0xffffffffu, sq, o);
    }
    __shared__ float ss[8], ssq[8];
    __shared__ float s_mu, s_r;
    if ((tid & 31) == 0) { ss[tid >> 5] = s; ssq[tid >> 5] = sq; }
    __syncthreads();
    if (tid == 0) {
        float S = 0.f, Q = 0.f;
        #pragma unroll
        for (int i = 0; i < 8; i++) { S += ss[i]; Q += ssq[i]; }
        float mu  = S * (1.0f / DMODEL);
        float var = Q * (1.0f / DMODEL) - mu * mu;
        s_mu = mu;
        s_r  = rsqrtf(var + 1e-5f);
    }
    __syncthreads();
    float mu = s_mu, r = s_r;
    float4 w4 = ((const float4*)w)[tid];
    float4 b4 = ((const float4*)b)[tid];
    float4 o4;
    o4.x = rtf((v.x - mu) * r * w4.x + b4.x);
    o4.y = rtf((v.y - mu) * r * w4.y + b4.y);
    o4.z = rtf((v.z - mu) * r * w4.z + b4.z);
    o4.w = rtf((v.w - mu) * r * w4.w + b4.w);
    ((float4*)(out + (size_t)row * DMODEL))[tid] = o4;
}

// ---------------------------------------------------------------------------
// tf32 mma.sync GEMM v3: 3-stage cp.async ring, one sync per stage.
// C[M,N] = A[M,K]@B[K,N] + bias; modes: 0 none, 1 relu+res, 2 gelu(->tf32), 3 +res
// ---------------------------------------------------------------------------
#define APITCH 36
#define BPITCH 136
#define ASTG (128 * APITCH)
#define BSTG (32 * BPITCH)
#define STG  (ASTG + BSTG)
#define GEMM_SMEM_BYTES (3 * STG * 4)

__global__ __launch_bounds__(256, 2) void tgemm_kernel(
    const float* __restrict__ A, const float* __restrict__ B,
    const float* __restrict__ bias, const float* __restrict__ res,
    float* __restrict__ C, int M, int N, int K, int mode)
{
    extern __shared__ float sm[];
    uint32_t smb = s2u(sm);

    int tid  = threadIdx.x;
    int lane = tid & 31;
    int wid  = tid >> 5;
    int wm   = wid >> 2;
    int wn   = wid & 3;
    int lr   = lane >> 2;
    int lc   = lane & 3;

    int bn = blockIdx.x * 128;
    int bm = blockIdx.y * 128;

    int arA[4], acA[4], krB[4], cnB[4];
    #pragma unroll
    for (int t = 0; t < 4; t++) {
        int idx = tid + t * 256;
        arA[t] = idx >> 3;  acA[t] = idx & 7;
        krB[t] = idx >> 5;  cnB[t] = idx & 31;
    }

    int mat = lane >> 3;
    int mrow = (lane & 7) + ((mat & 1) << 3);
    int makk = (mat >> 1) << 2;
    uint32_t aoff = (uint32_t)(((wm * 64 + mrow) * APITCH + makk) * 4);

    float acc[4][4][4];
    #pragma unroll
    for (int i = 0; i < 4; i++)
        #pragma unroll
        for (int j = 0; j < 4; j++)
            #pragma unroll
            for (int q = 0; q < 4; q++) acc[i][j][q] = 0.f;

    int NS = K >> 5;

    #pragma unroll
    for (int st = 0; st < 2; st++) {
        uint32_t Ab = smb + (uint32_t)st * STG * 4;
        uint32_t Bb = Ab + ASTG * 4;
        int k0 = st * 32;
        #pragma unroll
        for (int t = 0; t < 4; t++) {
            cpa16(Ab + (uint32_t)(arA[t] * APITCH + acA[t] * 4) * 4,
                  A + (size_t)(bm + arA[t]) * K + k0 + acA[t] * 4);
            cpa16(Bb + (uint32_t)(krB[t] * BPITCH + cnB[t] * 4) * 4,
                  B + (size_t)(k0 + krB[t]) * N + bn + cnB[t] * 4);
        }
        asm volatile("cp.async.commit_group;" ::: "memory");
    }

    for (int s = 0; s < NS; s++) {
        if (s + 1 < NS) asm volatile("cp.async.wait_group 1;" ::: "memory");
        else            asm volatile("cp.async.wait_group 0;" ::: "memory");
        __syncthreads();

        if (s + 2 < NS) {
            int b3 = (s + 2) % 3;
            uint32_t Ab = smb + (uint32_t)b3 * STG * 4;
            uint32_t Bb = Ab + ASTG * 4;
            int k0 = (s + 2) * 32;
            #pragma unroll
            for (int t = 0; t < 4; t++) {
                cpa16(Ab + (uint32_t)(arA[t] * APITCH + acA[t] * 4) * 4,
                      A + (size_t)(bm + arA[t]) * K + k0 + acA[t] * 4);
                cpa16(Bb + (uint32_t)(krB[t] * BPITCH + cnB[t] * 4) * 4,
                      B + (size_t)(k0 + krB[t]) * N + bn + cnB[t] * 4);
            }
            asm volatile("cp.async.commit_group;" ::: "memory");
        }

        int cb = s % 3;
        uint32_t Ab = smb + (uint32_t)cb * STG * 4;
        const uint32_t* Bs = (const uint32_t*)(sm + (size_t)cb * STG + ASTG);

        #pragma unroll
        for (int kk = 0; kk < 4; kk++) {
            uint32_t af[4][4];
            #pragma unroll
            for (int mt = 0; mt < 4; mt++) {
                uint32_t addr = Ab + aoff + (uint32_t)((mt * 16 * APITCH + kk * 8) * 4);
                asm volatile(
                    "ldmatrix.sync.aligned.m8n8.x4.shared.b16 {%0,%1,%2,%3}, [%4];"
                    : "=r"(af[mt][0]), "=r"(af[mt][1]), "=r"(af[mt][2]), "=r"(af[mt][3])
                    : "r"(addr));
            }
            uint32_t bf[4][2];
            int krow0 = (kk * 8 + lc) * BPITCH + wn * 32 + lr;
            #pragma unroll
            for (int nt = 0; nt < 4; nt++) {
                bf[nt][0] = Bs[krow0 + nt * 8];
                bf[nt][1] = Bs[krow0 + 4 * BPITCH + nt * 8];
            }
            #pragma unroll
            for (int mt = 0; mt < 4; mt++)
                #pragma unroll
                for (int nt = 0; nt < 4; nt++) {
                    asm volatile(
                        "mma.sync.aligned.m16n8k8.row.col.f32.tf32.tf32.f32 "
                        "{%0,%1,%2,%3}, {%4,%5,%6,%7}, {%8,%9}, {%0,%1,%2,%3};"
                        : "+f"(acc[mt][nt][0]), "+f"(acc[mt][nt][1]),
                          "+f"(acc[mt][nt][2]), "+f"(acc[mt][nt][3])
                        : "r"(af[mt][0]), "r"(af[mt][1]), "r"(af[mt][2]), "r"(af[mt][3]),
                          "r"(bf[nt][0]), "r"(bf[nt][1]));
                }
        }
    }

    // ---- epilogue ----
    #pragma unroll
    for (int mt = 0; mt < 4; mt++) {
        #pragma unroll
        for (int half = 0; half < 2; half++) {
            int row = bm + wm * 64 + mt * 16 + lr + half * 8;
            float* cr = C + (size_t)row * N;
            const float* rr = (mode == 1 || mode == 3) ? (res + (size_t)row * N) : nullptr;
            #pragma unroll
            for (int nt = 0; nt < 4; nt++) {
                int col = bn + wn * 32 + nt * 8 + lc * 2;
                float v0 = acc[mt][nt][half * 2 + 0] + bias[col];
                float v1 = acc[mt][nt][half * 2 + 1] + bias[col + 1];
                if (mode == 1) {
                    v0 = fmaxf(v0, 0.f) + rr[col];
                    v1 = fmaxf(v1, 0.f) + rr[col + 1];
                } else if (mode == 2) {
                    v0 = rtf(0.5f * v0 * (1.f + erff(v0 * 0.70710678118654752f)));
                    v1 = rtf(0.5f * v1 * (1.f + erff(v1 * 0.70710678118654752f)));
                } else if (mode == 3) {
                    v0 += rr[col];
                    v1 += rr[col + 1];
                }
                float2 o; o.x = v0; o.y = v1;
                *(float2*)(cr + col) = o;
            }
        }
    }
}

// ---------------------------------------------------------------------------
// Flash attention with mma.sync tf32.
// grid (S/128=8, B*H=128), 256 thr, 8 warps; warp owns 16 q-rows, KV tiles 64.
// QKV packed buffer: row stride 3072; q@col h*64, k@1024+h*64, v@2048+h*64.
// smem: sQ[128][68], sK[64][68], sV[64][72], sP[8][16][68]
// ---------------------------------------------------------------------------
#define QP 68
#define VP 72
#define SQ_OFF 0
#define SK_OFF (128 * QP)
#define SV_OFF (SK_OFF + 64 * QP)
#define SP_OFF (SV_OFF + 64 * VP)
#define ATTN_SMEM_FLOATS (SP_OFF + 8 * 16 * QP)

__global__ __launch_bounds__(256, 2) void attn_kernel(
    const float* __restrict__ QKV, float* __restrict__ Og)
{
    extern __shared__ float sm[];
    float* sQ = sm + SQ_OFF;
    float* sK = sm + SK_OFF;
    float* sV = sm + SV_OFF;

    int bh = blockIdx.y;
    int b  = bh >> 4;
    int h  = bh & 15;
    int q0 = blockIdx.x * 128;

    size_t base = (size_t)b * 1024 * 3072;
    const float* Qb = QKV + base + h * DKH;
    const float* Kb = QKV + base + 1024 + h * DKH;
    const float* Vb = QKV + base + 2048 + h * DKH;
    float* Ob = Og + (size_t)b * 1024 * DMODEL + h * DKH;

    int tid  = threadIdx.x;
    int lane = tid & 31;
    int wid  = tid >> 5;
    int lr   = lane >> 2;
    int lc   = lane & 3;

    int mat  = lane >> 3;
    int mrow = (lane & 7) + ((mat & 1) << 3);
    int makk = (mat >> 1) << 2;

    float* sPw = sm + SP_OFF + wid * 16 * QP;
    uint32_t sQb = s2u(sQ);
    uint32_t sPb = s2u(sPw);
    uint32_t aoffQ = (uint32_t)(((wid * 16 + mrow) * QP + makk) * 4);
    uint32_t aoffP = (uint32_t)((mrow * QP + makk) * 4);

    int rr = tid >> 4;           // 0..15
    int cc = (tid & 15) * 4;     // 0..60

    // load Q tile (128x64), scale 1/8, tf32-round
    #pragma unroll
    for (int it = 0; it < 8; it++) {
        int row = rr + it * 16;
        float4 v = *(const float4*)(Qb + (size_t)(q0 + row) * 3072 + cc);
        v.x = rtf(v.x * 0.125f); v.y = rtf(v.y * 0.125f);
        v.z = rtf(v.z * 0.125f); v.w = rtf(v.w * 0.125f);
        *(float4*)(sQ + row * QP + cc) = v;
    }

    float m0 = -1e30f, m1 = -1e30f, l0 = 0.f, l1 = 0.f;
    float o[8][4];
    #pragma unroll
    for (int nt = 0; nt < 8; nt++)
        #pragma unroll
        for (int q = 0; q < 4; q++) o[nt][q] = 0.f;

    for (int kt = 0; kt < 16; kt++) {
        __syncthreads();
        #pragma unroll
        for (int it = 0; it < 4; it++) {
            int j = rr + it * 16;
            float4 kv = *(const float4*)(Kb + (size_t)(kt * 64 + j) * 3072 + cc);
            kv.x = rtf(kv.x); kv.y = rtf(kv.y); kv.z = rtf(kv.z); kv.w = rtf(kv.w);
            *(float4*)(sK + j * QP + cc) = kv;
            float4 vv = *(const float4*)(Vb + (size_t)(kt * 64 + j) * 3072 + cc);
            vv.x = rtf(vv.x); vv.y = rtf(vv.y); vv.z = rtf(vv.z); vv.w = rtf(vv.w);
            *(float4*)(sV + j * VP + cc) = vv;
        }
        __syncthreads();

        // S = Q K^T : warp computes 16 x 64
        float sc[8][4];
        #pragma unroll
        for (int nt = 0; nt < 8; nt++)
            #pragma unroll
            for (int q = 0; q < 4; q++) sc[nt][q] = 0.f;

        #pragma unroll
        for (int kk = 0; kk < 8; kk++) {
            uint32_t a0, a1, a2, a3;
            asm volatile(
                "ldmatrix.sync.aligned.m8n8.x4.shared.b16 {%0,%1,%2,%3}, [%4];"
                : "=r"(a0), "=r"(a1), "=r"(a2), "=r"(a3)
                : "r"(sQb + aoffQ + (uint32_t)(kk * 32)));
            #pragma unroll
            for (int nt = 0; nt < 8; nt++) {
                uint32_t b0 = __float_as_uint(sK[(nt * 8 + lr) * QP + kk * 8 + lc]);
                uint32_t b1 = __float_as_uint(sK[(nt * 8 + lr) * QP + kk * 8 + lc + 4]);
                asm volatile(
                    "mma.sync.aligned.m16n8k8.row.col.f32.tf32.tf32.f32 "
                    "{%0,%1,%2,%3}, {%4,%5,%6,%7}, {%8,%9}, {%0,%1,%2,%3};"
                    : "+f"(sc[nt][0]), "+f"(sc[nt][1]), "+f"(sc[nt][2]), "+f"(sc[nt][3])
                    : "r"(a0), "r"(a1), "r"(a2), "r"(a3), "r"(b0), "r"(b1));
            }
        }

        // online softmax (rows lr and lr+8)
        float x0 = -1e30f, x1 = -1e30f;
        #pragma unroll
        for (int nt = 0; nt < 8; nt++) {
            x0 = fmaxf(x0, fmaxf(sc[nt][0], sc[nt][1]));
            x1 = fmaxf(x1, fmaxf(sc[nt][2], sc[nt][3]));
        }
        x0 = fmaxf(x0, __shfl_xor_sync(0xffffffffu, x0, 1));
        x0 = fmaxf(x0, __shfl_xor_sync(0xffffffffu, x0, 2));
        x1 = fmaxf(x1, __shfl_xor_sync(0xffffffffu, x1, 1));
        x1 = fmaxf(x1, __shfl_xor_sync(0xffffffffu, x1, 2));
        float mn0 = fmaxf(m0, x0), mn1 = fmaxf(m1, x1);
        float al0 = __expf(m0 - mn0), al1 = __expf(m1 - mn1);
        float su0 = 0.f, su1 = 0.f;
        #pragma unroll
        for (int nt = 0; nt < 8; nt++) {
            sc[nt][0] = __expf(sc[nt][0] - mn0);
            sc[nt][1] = __expf(sc[nt][1] - mn0);
            sc[nt][2] = __expf(sc[nt][2] - mn1);
            sc[nt][3] = __expf(sc[nt][3] - mn1);
            su0 += sc[nt][0] + sc[nt][1];
            su1 += sc[nt][2] + sc[nt][3];
            o[nt][0] *= al0; o[nt][1] *= al0;
            o[nt][2] *= al1; o[nt][3] *= al1;
        }
        su0 += __shfl_xor_sync(0xffffffffu, su0, 1);
        su0 += __shfl_xor_sync(0xffffffffu, su0, 2);
        su1 += __shfl_xor_sync(0xffffffffu, su1, 1);
        su1 += __shfl_xor_sync(0xffffffffu, su1, 2);
        l0 = l0 * al0 + su0;
        l1 = l1 * al1 + su1;
        m0 = mn0; m1 = mn1;

        // store P (tf32-rounded) to per-warp smem
        #pragma unroll
        for (int nt = 0; nt < 8; nt++) {
            float2 p01; p01.x = rtf(sc[nt][0]); p01.y = rtf(sc[nt][1]);
            float2 p23; p23.x = rtf(sc[nt][2]); p23.y = rtf(sc[nt][3]);
            *(float2*)(sPw + lr * QP + nt * 8 + lc * 2) = p01;
            *(float2*)(sPw + (lr + 8) * QP + nt * 8 + lc * 2) = p23;
        }
        __syncwarp();

        // O += P @ V
        #pragma unroll
        for (int kk = 0; kk < 8; kk++) {
            uint32_t a0, a1, a2, a3;
            asm volatile(
                "ldmatrix.sync.aligned.m8n8.x4.shared.b16 {%0,%1,%2,%3}, [%4];"
                : "=r"(a0), "=r"(a1), "=r"(a2), "=r"(a3)
                : "r"(sPb + aoffP + (uint32_t)(kk * 32)));
            #pragma unroll
            for (int nt = 0; nt < 8; nt++) {
                uint32_t b0 = __float_as_uint(sV[(kk * 8 + lc) * VP + nt * 8 + lr]);
                uint32_t b1 = __float_as_uint(sV[(kk * 8 + lc + 4) * VP + nt * 8 + lr]);
                asm volatile(
                    "mma.sync.aligned.m16n8k8.row.col.f32.tf32.tf32.f32 "
                    "{%0,%1,%2,%3}, {%4,%5,%6,%7}, {%8,%9}, {%0,%1,%2,%3};"
                    : "+f"(o[nt][0]), "+f"(o[nt][1]), "+f"(o[nt][2]), "+f"(o[nt][3])
                    : "r"(a0), "r"(a1), "r"(a2), "r"(a3), "r"(b0), "r"(b1));
            }
        }
        __syncwarp();
    }

    // epilogue: normalize + tf32-round + store
    float inv0 = 1.f / l0, inv1 = 1.f / l1;
    int row0 = q0 + wid * 16 + lr;
    int row1 = row0 + 8;
    #pragma unroll
    for (int nt = 0; nt < 8; nt++) {
        int col = nt * 8 + lc * 2;
        float2 r0v; r0v.x = rtf(o[nt][0] * inv0); r0v.y = rtf(o[nt][1] * inv0);
        float2 r1v; r1v.x = rtf(o[nt][2] * inv1); r1v.y = rtf(o[nt][3] * inv1);
        *(float2*)(Ob + (size_t)row0 * DMODEL + col) = r0v;
        *(float2*)(Ob + (size_t)row1 * DMODEL + col) = r1v;
    }
}

// ---------------------------------------------------------------------------
// Host launcher
// ---------------------------------------------------------------------------
extern "C" void kernel_launch(void* const* d_in, const int* in_sizes, int n_in,
                              void* d_out, int out_size)
{
    const float* x     = (const float*)d_in[0];
    const float* ln1_w = (const float*)d_in[1];
    const float* ln1_b = (const float*)d_in[2];
    const float* wq    = (const float*)d_in[3];
    const float* bq    = (const float*)d_in[4];
    const float* wk    = (const float*)d_in[5];
    const float* bk    = (const float*)d_in[6];
    const float* wv    = (const float*)d_in[7];
    const float* bv    = (const float*)d_in[8];
    const float* wo    = (const float*)d_in[9];
    const float* bo    = (const float*)d_in[10];
    const float* ln2_w = (const float*)d_in[11];
    const float* ln2_b = (const float*)d_in[12];
    const float* w1    = (const float*)d_in[13];
    const float* b1    = (const float*)d_in[14];
    const float* w2    = (const float*)d_in[15];
    const float* b2    = (const float*)d_in[16];

    float *p_h, *p_qkv, *p_ctx, *p_out1, *p_h2, *p_ff, *p_w;
    cudaGetSymbolAddress((void**)&p_h,    g_h);
    cudaGetSymbolAddress((void**)&p_qkv,  g_qkv);
    cudaGetSymbolAddress((void**)&p_ctx,  g_ctx);
    cudaGetSymbolAddress((void**)&p_out1, g_out1);
    cudaGetSymbolAddress((void**)&p_h2,   g_h2);
    cudaGetSymbolAddress((void**)&p_ff,   g_ff);
    cudaGetSymbolAddress((void**)&p_w,    g_wbuf);

    const int MB = 1024 * 1024;
    float* rwqkv = p_w;                 // [1024][3072]
    float* rwo   = p_w + 3 * MB;
    float* rw1   = p_w + 4 * MB;
    float* rw2   = p_w + 8 * MB;
    float* bqkv  = p_w + 12 * MB;

    cudaFuncSetAttribute(attn_kernel, cudaFuncAttributeMaxDynamicSharedMemorySize,
                         ATTN_SMEM_FLOATS * 4);
    cudaFuncSetAttribute(tgemm_kernel, cudaFuncAttributeMaxDynamicSharedMemorySize,
                         GEMM_SMEM_BYTES);

    // 0) weight pre-round / pack
    packw_kernel<<<1024, 256>>>(wq, rwqkv, 0);
    packw_kernel<<<1024, 256>>>(wk, rwqkv, 1024);
    packw_kernel<<<1024, 256>>>(wv, rwqkv, 2048);
    packb_kernel<<<12, 256>>>(bq, bk, bv, bqkv);
    round_kernel<<<(MB / 4 + 255) / 256, 256>>>(wo, rwo, MB / 4);
    round_kernel<<<(4 * MB / 4 + 255) / 256, 256>>>(w1, rw1, 4 * MB / 4);
    round_kernel<<<(4 * MB / 4 + 255) / 256, 256>>>(w2, rw2, 4 * MB / 4);

    // 1) ln1
    ln_kernel<<<TOK, 256>>>(x, ln1_w, ln1_b, p_h);
    // 2) fused QKV projection: [8192,1024]@[1024,3072]
    tgemm_kernel<<<dim3(24, 64), 256, GEMM_SMEM_BYTES>>>(p_h, rwqkv, bqkv, nullptr, p_qkv, TOK, 3 * DMODEL, DMODEL, 0);
    // 3) attention (tf32 mma)
    attn_kernel<<<dim3(8, 128), 256, ATTN_SMEM_FLOATS * 4>>>(p_qkv, p_ctx);
    // 4) out proj + relu + residual(x)
    tgemm_kernel<<<dim3(8, 64), 256, GEMM_SMEM_BYTES>>>(p_ctx, rwo, bo, x, p_out1, TOK, DMODEL, DMODEL, 1);
    // 5) ln2
    ln_kernel<<<TOK, 256>>>(p_out1, ln2_w, ln2_b, p_h2);
    // 6) MLP up + gelu
    tgemm_kernel<<<dim3(32, 64), 256, GEMM_SMEM_BYTES>>>(p_h2, rw1, b1, nullptr, p_ff, TOK, DMLP, DMODEL, 2);
    // 7) MLP down + residual(out1) -> d_out
    tgemm_kernel<<<dim3(8, 64), 256, GEMM_SMEM_BYTES>>>(p_ff, rw2, b2, p_out1, (float*)d_out, TOK, DMODEL, DMLP, 3);
}

// round 7
// speedup vs baseline: 3.7788x; 1.0280x over previous
#include <cuda_runtime.h>
#include <cuda_bf16.h>
#include <math.h>
#include <stdint.h>

// ---------------------------------------------------------------------------
// Problem constants: B=8, S=1024, D=1024, H=16, DK=64, MLP=4096, tokens=8192
// ---------------------------------------------------------------------------
#define TOK    8192
#define DMODEL 1024
#define NHEAD  16
#define DKH    64
#define DMLP   4096

// ---------------------------------------------------------------------------
// Scratch (device globals; no allocation allowed)
// ---------------------------------------------------------------------------
__device__ float g_h   [TOK * DMODEL];
__device__ float g_qkv [TOK * 3 * DMODEL];
__device__ float g_ctx [TOK * DMODEL];
__device__ float g_out1[TOK * DMODEL];
__device__ float g_h2  [TOK * DMODEL];
__device__ float g_ff  [TOK * DMLP];
__device__ float g_wbuf[13 * 1024 * 1024];  // wqkvT(3M) woT(1M) w1T(4M) w2T(4M) bqkv

__device__ __forceinline__ uint32_t f2tf32(float x) {
    uint32_t r; asm("cvt.rna.tf32.f32 %0, %1;" : "=r"(r) : "f"(x)); return r;
}
__device__ __forceinline__ float rtf(float x) { return __uint_as_float(f2tf32(x)); }
__device__ __forceinline__ uint32_t s2u(const void* p) {
    uint32_t a;
    asm("{ .reg .u64 t; cvta.to.shared.u64 t, %1; cvt.u32.u64 %0, t; }" : "=r"(a) : "l"(p));
    return a;
}
__device__ __forceinline__ void cpa16(uint32_t dst, const void* src) {
    asm volatile("cp.async.cg.shared.global [%0], [%1], 16;" :: "r"(dst), "l"(src) : "memory");
}

// ---------------------------------------------------------------------------
// Weight prep: transpose [K][N] -> [N][K] with tf32 rounding.
// dst row n goes to (roff + n), dst pitch = Kd.
// ---------------------------------------------------------------------------
__global__ __launch_bounds__(256) void transw_kernel(
    const float* __restrict__ src, float* __restrict__ dst,
    int Kd, int Nd, int roff)
{
    __shared__ float t[32][33];
    int n0 = blockIdx.x * 32, k0 = blockIdx.y * 32;
    int tx = threadIdx.x, ty = threadIdx.y;
    #pragma unroll
    for (int i = 0; i < 32; i += 8)
        t[ty + i][tx] = rtf(src[(size_t)(k0 + ty + i) * Nd + n0 + tx]);
    __syncthreads();
    #pragma unroll
    for (int i = 0; i < 32; i += 8)
        dst[(size_t)(roff + n0 + ty + i) * Kd + k0 + tx] = t[tx][ty + i];
}
__global__ __launch_bounds__(256) void packb_kernel(
    const float* __restrict__ bq, const float* __restrict__ bk,
    const float* __restrict__ bv, float* __restrict__ dst)
{
    int i = blockIdx.x * 256 + threadIdx.x;
    if (i < 3072)
        dst[i] = (i < 1024) ? bq[i] : (i < 2048) ? bk[i - 1024] : bv[i - 2048];
}

// ---------------------------------------------------------------------------
// LayerNorm: one block per row (D=1024), 256 threads, float4, tf32-rounded out
// ---------------------------------------------------------------------------
__global__ __launch_bounds__(256) void ln_kernel(
    const float* __restrict__ x, const float* __restrict__ w,
    const float* __restrict__ b, float* __restrict__ out)
{
    int row = blockIdx.x;
    int tid = threadIdx.x;
    const float4* xr = (const float4*)(x + (size_t)row * DMODEL);
    float4 v = xr[tid];
    float s  = v.x + v.y + v.z + v.w;
    float sq = v.x*v.x + v.y*v.y + v.z*v.z + v.w*v.w;
    #pragma unroll
    for (int o = 16; o; o >>= 1) {
        s  += __shfl_xor_sync(0xffffffffu, s,  o);
        sq += __shfl_xor_sync(0xffffffffu, sq, o);
    }
    __shared__ float ss[8], ssq[8];
    __shared__ float s_mu, s_r;
    if ((tid & 31) == 0) { ss[tid >> 5] = s; ssq[tid >> 5] = sq; }
    __syncthreads();
    if (tid == 0) {
        float S = 0.f, Q = 0.f;
        #pragma unroll
        for (int i = 0; i < 8; i++) { S += ss[i]; Q += ssq[i]; }
        float mu  = S * (1.0f / DMODEL);
        float var = Q * (1.0f / DMODEL) - mu * mu;
        s_mu = mu;
        s_r  = rsqrtf(var + 1e-5f);
    }
    __syncthreads();
    float mu = s_mu, r = s_r;
    float4 w4 = ((const float4*)w)[tid];
    float4 b4 = ((const float4*)b)[tid];
    float4 o4;
    o4.x = rtf((v.x - mu) * r * w4.x + b4.x);
    o4.y = rtf((v.y - mu) * r * w4.y + b4.y);
    o4.z = rtf((v.z - mu) * r * w4.z + b4.z);
    o4.w = rtf((v.w - mu) * r * w4.w + b4.w);
    ((float4*)(out + (size_t)row * DMODEL))[tid] = o4;
}

// ---------------------------------------------------------------------------
// tf32 mma.sync GEMM v4: B pre-transposed [N][K]; both tiles [128][36];
// all fragments via ldmatrix. 3-stage cp.async ring.
// C[M,N]=A[M,K]@Bt^T + bias; modes: 0 none, 1 relu+res, 2 gelu(->tf32), 3 +res
// ---------------------------------------------------------------------------
#define APITCH 36
#define ASTG (128 * APITCH)
#define STG  (2 * ASTG)
#define GEMM_SMEM_BYTES (3 * STG * 4)

__global__ __launch_bounds__(256, 2) void tgemm_kernel(
    const float* __restrict__ A, const float* __restrict__ Bt,
    const float* __restrict__ bias, const float* __restrict__ res,
    float* __restrict__ C, int M, int N, int K, int mode)
{
    extern __shared__ float sm[];
    uint32_t smb = s2u(sm);

    int tid  = threadIdx.x;
    int lane = tid & 31;
    int wid  = tid >> 5;
    int wm   = wid >> 2;
    int wn   = wid & 3;
    int lr   = lane >> 2;
    int lc   = lane & 3;

    int bn = blockIdx.x * 128;
    int bm = blockIdx.y * 128;

    int arA[4], acA[4];
    #pragma unroll
    for (int t = 0; t < 4; t++) {
        int idx = tid + t * 256;
        arA[t] = idx >> 3;  acA[t] = idx & 7;
    }

    // ldmatrix lane addressing
    int mat = lane >> 3;
    int mrow = (lane & 7) + ((mat & 1) << 3);
    int makk = (mat >> 1) << 2;
    uint32_t aoff = (uint32_t)(((wm * 64 + mrow) * APITCH + makk) * 4);
    // B: mats {n0 k0, n0 k4, n8 k0, n8 k4}
    int bmu = lane >> 3, br = lane & 7;
    uint32_t boff = (uint32_t)(((wn * 32 + ((bmu >> 1) << 3) + br) * APITCH
                               + ((bmu & 1) << 2)) * 4);

    float acc[4][4][4];
    #pragma unroll
    for (int i = 0; i < 4; i++)
        #pragma unroll
        for (int j = 0; j < 4; j++)
            #pragma unroll
            for (int q = 0; q < 4; q++) acc[i][j][q] = 0.f;

    int NS = K >> 5;

    #pragma unroll
    for (int st = 0; st < 2; st++) {
        uint32_t Ab = smb + (uint32_t)st * STG * 4;
        uint32_t Bb = Ab + ASTG * 4;
        int k0 = st * 32;
        #pragma unroll
        for (int t = 0; t < 4; t++) {
            cpa16(Ab + (uint32_t)(arA[t] * APITCH + acA[t] * 4) * 4,
                  A + (size_t)(bm + arA[t]) * K + k0 + acA[t] * 4);
            cpa16(Bb + (uint32_t)(arA[t] * APITCH + acA[t] * 4) * 4,
                  Bt + (size_t)(bn + arA[t]) * K + k0 + acA[t] * 4);
        }
        asm volatile("cp.async.commit_group;" ::: "memory");
    }

    for (int s = 0; s < NS; s++) {
        if (s + 1 < NS) asm volatile("cp.async.wait_group 1;" ::: "memory");
        else            asm volatile("cp.async.wait_group 0;" ::: "memory");
        __syncthreads();

        if (s + 2 < NS) {
            int b3 = (s + 2) % 3;
            uint32_t Ab = smb + (uint32_t)b3 * STG * 4;
            uint32_t Bb = Ab + ASTG * 4;
            int k0 = (s + 2) * 32;
            #pragma unroll
            for (int t = 0; t < 4; t++) {
                cpa16(Ab + (uint32_t)(arA[t] * APITCH + acA[t] * 4) * 4,
                      A + (size_t)(bm + arA[t]) * K + k0 + acA[t] * 4);
                cpa16(Bb + (uint32_t)(arA[t] * APITCH + acA[t] * 4) * 4,
                      Bt + (size_t)(bn + arA[t]) * K + k0 + acA[t] * 4);
            }
            asm volatile("cp.async.commit_group;" ::: "memory");
        }

        int cb = s % 3;
        uint32_t Ab = smb + (uint32_t)cb * STG * 4;
        uint32_t Bb = Ab + ASTG * 4;

        #pragma unroll
        for (int kk = 0; kk < 4; kk++) {
            uint32_t af[4][4];
            #pragma unroll
            for (int mt = 0; mt < 4; mt++) {
                asm volatile(
                    "ldmatrix.sync.aligned.m8n8.x4.shared.b16 {%0,%1,%2,%3}, [%4];"
                    : "=r"(af[mt][0]), "=r"(af[mt][1]), "=r"(af[mt][2]), "=r"(af[mt][3])
                    : "r"(Ab + aoff + (uint32_t)((mt * 16 * APITCH + kk * 8) * 4)));
            }
            uint32_t bf[4][2];
            #pragma unroll
            for (int p = 0; p < 2; p++) {
                asm volatile(
                    "ldmatrix.sync.aligned.m8n8.x4.shared.b16 {%0,%1,%2,%3}, [%4];"
                    : "=r"(bf[2*p][0]), "=r"(bf[2*p][1]),
                      "=r"(bf[2*p+1][0]), "=r"(bf[2*p+1][1])
                    : "r"(Bb + boff + (uint32_t)((p * 16 * APITCH + kk * 8) * 4)));
            }
            #pragma unroll
            for (int mt = 0; mt < 4; mt++)
                #pragma unroll
                for (int nt = 0; nt < 4; nt++) {
                    asm volatile(
                        "mma.sync.aligned.m16n8k8.row.col.f32.tf32.tf32.f32 "
                        "{%0,%1,%2,%3}, {%4,%5,%6,%7}, {%8,%9}, {%0,%1,%2,%3};"
                        : "+f"(acc[mt][nt][0]), "+f"(acc[mt][nt][1]),
                          "+f"(acc[mt][nt][2]), "+f"(acc[mt][nt][3])
                        : "r"(af[mt][0]), "r"(af[mt][1]), "r"(af[mt][2]), "r"(af[mt][3]),
                          "r"(bf[nt][0]), "r"(bf[nt][1]));
                }
        }
    }

    // ---- epilogue ----
    #pragma unroll
    for (int mt = 0; mt < 4; mt++) {
        #pragma unroll
        for (int half = 0; half < 2; half++) {
            int row = bm + wm * 64 + mt * 16 + lr + half * 8;
            float* cr = C + (size_t)row * N;
            const float* rr = (mode == 1 || mode == 3) ? (res + (size_t)row * N) : nullptr;
            #pragma unroll
            for (int nt = 0; nt < 4; nt++) {
                int col = bn + wn * 32 + nt * 8 + lc * 2;
                float v0 = acc[mt][nt][half * 2 + 0] + bias[col];
                float v1 = acc[mt][nt][half * 2 + 1] + bias[col + 1];
                if (mode == 1) {
                    v0 = fmaxf(v0, 0.f) + rr[col];
                    v1 = fmaxf(v1, 0.f) + rr[col + 1];
                } else if (mode == 2) {
                    v0 = rtf(0.5f * v0 * (1.f + erff(v0 * 0.70710678118654752f)));
                    v1 = rtf(0.5f * v1 * (1.f + erff(v1 * 0.70710678118654752f)));
                } else if (mode == 3) {
                    v0 += rr[col];
                    v1 += rr[col + 1];
                }
                float2 o; o.x = v0; o.y = v1;
                *(float2*)(cr + col) = o;
            }
        }
    }
}

// ---------------------------------------------------------------------------
// Flash attention with mma.sync tf32 (K-frags now via ldmatrix).
// grid (S/128=8, B*H=128), 256 thr, 8 warps; warp owns 16 q-rows, KV tiles 64.
// smem: sQ[128][68], sK[64][68], sV[64][72], sP[8][16][68]
// ---------------------------------------------------------------------------
#define QP 68
#define VP 72
#define SQ_OFF 0
#define SK_OFF (128 * QP)
#define SV_OFF (SK_OFF + 64 * QP)
#define SP_OFF (SV_OFF + 64 * VP)
#define ATTN_SMEM_FLOATS (SP_OFF + 8 * 16 * QP)

__global__ __launch_bounds__(256, 2) void attn_kernel(
    const float* __restrict__ QKV, float* __restrict__ Og)
{
    extern __shared__ float sm[];
    float* sQ = sm + SQ_OFF;
    float* sK = sm + SK_OFF;
    float* sV = sm + SV_OFF;

    int bh = blockIdx.y;
    int b  = bh >> 4;
    int h  = bh & 15;
    int q0 = blockIdx.x * 128;

    size_t base = (size_t)b * 1024 * 3072;
    const float* Qb = QKV + base + h * DKH;
    const float* Kb = QKV + base + 1024 + h * DKH;
    const float* Vb = QKV + base + 2048 + h * DKH;
    float* Ob = Og + (size_t)b * 1024 * DMODEL + h * DKH;

    int tid  = threadIdx.x;
    int lane = tid & 31;
    int wid  = tid >> 5;
    int lr   = lane >> 2;
    int lc   = lane & 3;

    int mat  = lane >> 3;
    int mrow = (lane & 7) + ((mat & 1) << 3);
    int makk = (mat >> 1) << 2;

    float* sPw = sm + SP_OFF + wid * 16 * QP;
    uint32_t sQb = s2u(sQ);
    uint32_t sKb = s2u(sK);
    uint32_t sPb = s2u(sPw);
    uint32_t aoffQ = (uint32_t)(((wid * 16 + mrow) * QP + makk) * 4);
    uint32_t aoffP = (uint32_t)((mrow * QP + makk) * 4);
    int bmu = lane >> 3, brr = lane & 7;
    uint32_t koff = (uint32_t)(((((bmu >> 1) << 3) + brr) * QP + ((bmu & 1) << 2)) * 4);

    int rr = tid >> 4;           // 0..15
    int cc = (tid & 15) * 4;     // 0..60

    // load Q tile (128x64), scale 1/8, tf32-round
    #pragma unroll
    for (int it = 0; it < 8; it++) {
        int row = rr + it * 16;
        float4 v = *(const float4*)(Qb + (size_t)(q0 + row) * 3072 + cc);
        v.x = rtf(v.x * 0.125f); v.y = rtf(v.y * 0.125f);
        v.z = rtf(v.z * 0.125f); v.w = rtf(v.w * 0.125f);
        *(float4*)(sQ + row * QP + cc) = v;
    }

    float m0 = -1e30f, m1 = -1e30f, l0 = 0.f, l1 = 0.f;
    float o[8][4];
    #pragma unroll
    for (int nt = 0; nt < 8; nt++)
        #pragma unroll
        for (int q = 0; q < 4; q++) o[nt][q] = 0.f;

    for (int kt = 0; kt < 16; kt++) {
        __syncthreads();
        #pragma unroll
        for (int it = 0; it < 4; it++) {
            int j = rr + it * 16;
            float4 kv = *(const float4*)(Kb + (size_t)(kt * 64 + j) * 3072 + cc);
            kv.x = rtf(kv.x); kv.y = rtf(kv.y); kv.z = rtf(kv.z); kv.w = rtf(kv.w);
            *(float4*)(sK + j * QP + cc) = kv;
            float4 vv = *(const float4*)(Vb + (size_t)(kt * 64 + j) * 3072 + cc);
            vv.x = rtf(vv.x); vv.y = rtf(vv.y); vv.z = rtf(vv.z); vv.w = rtf(vv.w);
            *(float4*)(sV + j * VP + cc) = vv;
        }
        __syncthreads();

        // S = Q K^T : warp computes 16 x 64
        float sc[8][4];
        #pragma unroll
        for (int nt = 0; nt < 8; nt++)
            #pragma unroll
            for (int q = 0; q < 4; q++) sc[nt][q] = 0.f;

        #pragma unroll
        for (int kk = 0; kk < 8; kk++) {
            uint32_t a0, a1, a2, a3;
            asm volatile(
                "ldmatrix.sync.aligned.m8n8.x4.shared.b16 {%0,%1,%2,%3}, [%4];"
                : "=r"(a0), "=r"(a1), "=r"(a2), "=r"(a3)
                : "r"(sQb + aoffQ + (uint32_t)(kk * 32)));
            uint32_t kf[8][2];
            #pragma unroll
            for (int p = 0; p < 4; p++) {
                asm volatile(
                    "ldmatrix.sync.aligned.m8n8.x4.shared.b16 {%0,%1,%2,%3}, [%4];"
                    : "=r"(kf[2*p][0]), "=r"(kf[2*p][1]),
                      "=r"(kf[2*p+1][0]), "=r"(kf[2*p+1][1])
                    : "r"(sKb + koff + (uint32_t)((p * 16 * QP + kk * 8) * 4)));
            }
            #pragma unroll
            for (int nt = 0; nt < 8; nt++) {
                asm volatile(
                    "mma.sync.aligned.m16n8k8.row.col.f32.tf32.tf32.f32 "
                    "{%0,%1,%2,%3}, {%4,%5,%6,%7}, {%8,%9}, {%0,%1,%2,%3};"
                    : "+f"(sc[nt][0]), "+f"(sc[nt][1]), "+f"(sc[nt][2]), "+f"(sc[nt][3])
                    : "r"(a0), "r"(a1), "r"(a2), "r"(a3),
                      "r"(kf[nt][0]), "r"(kf[nt][1]));
            }
        }

        // online softmax (rows lr and lr+8)
        float x0 = -1e30f, x1 = -1e30f;
        #pragma unroll
        for (int nt = 0; nt < 8; nt++) {
            x0 = fmaxf(x0, fmaxf(sc[nt][0], sc[nt][1]));
            x1 = fmaxf(x1, fmaxf(sc[nt][2], sc[nt][3]));
        }
        x0 = fmaxf(x0, __shfl_xor_sync(0xffffffffu, x0, 1));
        x0 = fmaxf(x0, __shfl_xor_sync(0xffffffffu, x0, 2));
        x1 = fmaxf(x1, __shfl_xor_sync(0xffffffffu, x1, 1));
        x1 = fmaxf(x1, __shfl_xor_sync(0xffffffffu, x1, 2));
        float mn0 = fmaxf(m0, x0), mn1 = fmaxf(m1, x1);
        float al0 = __expf(m0 - mn0), al1 = __expf(m1 - mn1);
        float su0 = 0.f, su1 = 0.f;
        #pragma unroll
        for (int nt = 0; nt < 8; nt++) {
            sc[nt][0] = __expf(sc[nt][0] - mn0);
            sc[nt][1] = __expf(sc[nt][1] - mn0);
            sc[nt][2] = __expf(sc[nt][2] - mn1);
            sc[nt][3] = __expf(sc[nt][3] - mn1);
            su0 += sc[nt][0] + sc[nt][1];
            su1 += sc[nt][2] + sc[nt][3];
            o[nt][0] *= al0; o[nt][1] *= al0;
            o[nt][2] *= al1; o[nt][3] *= al1;
        }
        su0 += __shfl_xor_sync(0xffffffffu, su0, 1);
        su0 += __shfl_xor_sync(0xffffffffu, su0, 2);
        su1 += __shfl_xor_sync(0xffffffffu, su1, 1);
        su1 += __shfl_xor_sync(0xffffffffu, su1, 2);
        l0 = l0 * al0 + su0;
        l1 = l1 * al1 + su1;
        m0 = mn0; m1 = mn1;

        // store P (tf32-rounded) to per-warp smem
        #pragma unroll
        for (int nt = 0; nt < 8; nt++) {
            float2 p01; p01.x = rtf(sc[nt][0]); p01.y = rtf(sc[nt][1]);
            float2 p23; p23.x = rtf(sc[nt][2]); p23.y = rtf(sc[nt][3]);
            *(float2*)(sPw + lr * QP + nt * 8 + lc * 2) = p01;
            *(float2*)(sPw + (lr + 8) * QP + nt * 8 + lc * 2) = p23;
        }
        __syncwarp();

        // O += P @ V
        #pragma unroll
        for (int kk = 0; kk < 8; kk++) {
            uint32_t a0, a1, a2, a3;
            asm volatile(
                "ldmatrix.sync.aligned.m8n8.x4.shared.b16 {%0,%1,%2,%3}, [%4];"
                : "=r"(a0), "=r"(a1), "=r"(a2), "=r"(a3)
                : "r"(sPb + aoffP + (uint32_t)(kk * 32)));
            #pragma unroll
            for (int nt = 0; nt < 8; nt++) {
                uint32_t b0 = __float_as_uint(sV[(kk * 8 + lc) * VP + nt * 8 + lr]);
                uint32_t b1 = __float_as_uint(sV[(kk * 8 + lc + 4) * VP + nt * 8 + lr]);
                asm volatile(
                    "mma.sync.aligned.m16n8k8.row.col.f32.tf32.tf32.f32 "
                    "{%0,%1,%2,%3}, {%4,%5,%6,%7}, {%8,%9}, {%0,%1,%2,%3};"
                    : "+f"(o[nt][0]), "+f"(o[nt][1]), "+f"(o[nt][2]), "+f"(o[nt][3])
                    : "r"(a0), "r"(a1), "r"(a2), "r"(a3), "r"(b0), "r"(b1));
            }
        }
        __syncwarp();
    }

    // epilogue: normalize + tf32-round + store
    float inv0 = 1.f / l0, inv1 = 1.f / l1;
    int row0 = q0 + wid * 16 + lr;
    int row1 = row0 + 8;
    #pragma unroll
    for (int nt = 0; nt < 8; nt++) {
        int col = nt * 8 + lc * 2;
        float2 r0v; r0v.x = rtf(o[nt][0] * inv0); r0v.y = rtf(o[nt][1] * inv0);
        float2 r1v; r1v.x = rtf(o[nt][2] * inv1); r1v.y = rtf(o[nt][3] * inv1);
        *(float2*)(Ob + (size_t)row0 * DMODEL + col) = r0v;
        *(float2*)(Ob + (size_t)row1 * DMODEL + col) = r1v;
    }
}

// ---------------------------------------------------------------------------
// Host launcher
// ---------------------------------------------------------------------------
extern "C" void kernel_launch(void* const* d_in, const int* in_sizes, int n_in,
                              void* d_out, int out_size)
{
    const float* x     = (const float*)d_in[0];
    const float* ln1_w = (const float*)d_in[1];
    const float* ln1_b = (const float*)d_in[2];
    const float* wq    = (const float*)d_in[3];
    const float* bq    = (const float*)d_in[4];
    const float* wk    = (const float*)d_in[5];
    const float* bk    = (const float*)d_in[6];
    const float* wv    = (const float*)d_in[7];
    const float* bv    = (const float*)d_in[8];
    const float* wo    = (const float*)d_in[9];
    const float* bo    = (const float*)d_in[10];
    const float* ln2_w = (const float*)d_in[11];
    const float* ln2_b = (const float*)d_in[12];
    const float* w1    = (const float*)d_in[13];
    const float* b1    = (const float*)d_in[14];
    const float* w2    = (const float*)d_in[15];
    const float* b2    = (const float*)d_in[16];

    float *p_h, *p_qkv, *p_ctx, *p_out1, *p_h2, *p_ff, *p_w;
    cudaGetSymbolAddress((void**)&p_h,    g_h);
    cudaGetSymbolAddress((void**)&p_qkv,  g_qkv);
    cudaGetSymbolAddress((void**)&p_ctx,  g_ctx);
    cudaGetSymbolAddress((void**)&p_out1, g_out1);
    cudaGetSymbolAddress((void**)&p_h2,   g_h2);
    cudaGetSymbolAddress((void**)&p_ff,   g_ff);
    cudaGetSymbolAddress((void**)&p_w,    g_wbuf);

    const int MB = 1024 * 1024;
    float* wqkvT = p_w;                 // [3072][1024]
    float* woT   = p_w + 3 * MB;        // [1024][1024]
    float* w1T   = p_w + 4 * MB;        // [4096][1024]
    float* w2T   = p_w + 8 * MB;        // [1024][4096]
    float* bqkv  = p_w + 12 * MB;

    cudaFuncSetAttribute(attn_kernel, cudaFuncAttributeMaxDynamicSharedMemorySize,
                         ATTN_SMEM_FLOATS * 4);
    cudaFuncSetAttribute(tgemm_kernel, cudaFuncAttributeMaxDynamicSharedMemorySize,
                         GEMM_SMEM_BYTES);

    // 0) weight prep: transpose + tf32-round
    transw_kernel<<<dim3(32, 32), dim3(32, 8)>>>(wq, wqkvT, 1024, 1024, 0);
    transw_kernel<<<dim3(32, 32), dim3(32, 8)>>>(wk, wqkvT, 1024, 1024, 1024);
    transw_kernel<<<dim3(32, 32), dim3(32, 8)>>>(wv, wqkvT, 1024, 1024, 2048);
    transw_kernel<<<dim3(32, 32), dim3(32, 8)>>>(wo, woT, 1024, 1024, 0);
    transw_kernel<<<dim3(128, 32), dim3(32, 8)>>>(w1, w1T, 1024, 4096, 0);
    transw_kernel<<<dim3(32, 128), dim3(32, 8)>>>(w2, w2T, 4096, 1024, 0);
    packb_kernel<<<12, 256>>>(bq, bk, bv, bqkv);

    // 1) ln1
    ln_kernel<<<TOK, 256>>>(x, ln1_w, ln1_b, p_h);
    // 2) fused QKV projection: [8192,1024]@[1024,3072]
    tgemm_kernel<<<dim3(24, 64), 256, GEMM_SMEM_BYTES>>>(p_h, wqkvT, bqkv, nullptr, p_qkv, TOK, 3 * DMODEL, DMODEL, 0);
    // 3) attention (tf32 mma)
    attn_kernel<<<dim3(8, 128), 256, ATTN_SMEM_FLOATS * 4>>>(p_qkv, p_ctx);
    // 4) out proj + relu + residual(x)
    tgemm_kernel<<<dim3(8, 64), 256, GEMM_SMEM_BYTES>>>(p_ctx, woT, bo, x, p_out1, TOK, DMODEL, DMODEL, 1);
    // 5) ln2
    ln_kernel<<<TOK, 256>>>(p_out1, ln2_w, ln2_b, p_h2);
    // 6) MLP up + gelu
    tgemm_kernel<<<dim3(32, 64), 256, GEMM_SMEM_BYTES>>>(p_h2, w1T, b1, nullptr, p_ff, TOK, DMLP, DMODEL, 2);
    // 7) MLP down + residual(out1) -> d_out
    tgemm_kernel<<<dim3(8, 64), 256, GEMM_SMEM_BYTES>>>(p_ff, w2T, b2, p_out1, (float*)d_out, TOK, DMODEL, DMLP, 3);
}

// round 11
// speedup vs baseline: 6.9371x; 1.8358x over previous
#include <cuda_runtime.h>
#include <cuda_fp16.h>
#include <math.h>
#include <stdint.h>

// ---------------------------------------------------------------------------
// Problem constants: B=8, S=1024, D=1024, H=16, DK=64, MLP=4096, tokens=8192
// ---------------------------------------------------------------------------
#define TOK    8192
#define DMODEL 1024
#define NHEAD  16
#define DKH    64
#define DMLP   4096

// ---------------------------------------------------------------------------
// Scratch (device globals; no allocation allowed)
// ---------------------------------------------------------------------------
__device__ __half g_h   [TOK * DMODEL];
__device__ __half g_qkv [TOK * 3 * DMODEL];
__device__ __half g_ctx [TOK * DMODEL];
__device__ float  g_out1[TOK * DMODEL];
__device__ __half g_h2  [TOK * DMODEL];
__device__ __half g_ff  [TOK * DMLP];
__device__ __half g_wh  [12 * 1024 * 1024];  // wqkvT(3M) woT(1M) w1T(4M) w2T(4M)
__device__ float  g_bqkv[3072];

__device__ __forceinline__ uint32_t s2u(const void* p) {
    uint32_t a;
    asm("{ .reg .u64 t; cvta.to.shared.u64 t, %1; cvt.u32.u64 %0, t; }" : "=r"(a) : "l"(p));
    return a;
}
__device__ __forceinline__ void cpa16(uint32_t dst, const void* src) {
    asm volatile("cp.async.cg.shared.global [%0], [%1], 16;" :: "r"(dst), "l"(src) : "memory");
}
__device__ __forceinline__ uint32_t h2u(__half2 h) {
    union { __half2 h; uint32_t u; } c; c.h = h; return c.u;
}

// ---------------------------------------------------------------------------
// Weight prep: transpose [Kd][Nd] fp32 -> [Nd][Kd] half (row n at roff+n), *scale
// ---------------------------------------------------------------------------
__global__ __launch_bounds__(256) void transw_kernel(
    const float* __restrict__ src, __half* __restrict__ dst,
    int Kd, int Nd, int roff, float scale)
{
    __shared__ float t[32][33];
    int n0 = blockIdx.x * 32, k0 = blockIdx.y * 32;
    int tx = threadIdx.x, ty = threadIdx.y;
    #pragma unroll
    for (int i = 0; i < 32; i += 8)
        t[ty + i][tx] = src[(size_t)(k0 + ty + i) * Nd + n0 + tx] * scale;
    __syncthreads();
    #pragma unroll
    for (int i = 0; i < 32; i += 8)
        dst[(size_t)(roff + n0 + ty + i) * Kd + k0 + tx] = __float2half_rn(t[tx][ty + i]);
}
__global__ __launch_bounds__(256) void packb_kernel(
    const float* __restrict__ bq, const float* __restrict__ bk,
    const float* __restrict__ bv, float* __restrict__ dst)
{
    int i = blockIdx.x * 256 + threadIdx.x;
    if (i < 3072)
        dst[i] = (i < 1024) ? bq[i] * 0.125f : (i < 2048) ? bk[i - 1024] : bv[i - 2048];
}

// ---------------------------------------------------------------------------
// LayerNorm: fp32 in, half out. One block per row, 256 threads.
// ---------------------------------------------------------------------------
__global__ __launch_bounds__(256) void ln_kernel(
    const float* __restrict__ x, const float* __restrict__ w,
    const float* __restrict__ b, __half* __restrict__ out)
{
    int row = blockIdx.x;
    int tid = threadIdx.x;
    const float4* xr = (const float4*)(x + (size_t)row * DMODEL);
    float4 v = xr[tid];
    float s  = v.x + v.y + v.z + v.w;
    float sq = v.x*v.x + v.y*v.y + v.z*v.z + v.w*v.w;
    #pragma unroll
    for (int o = 16; o; o >>= 1) {
        s  += __shfl_xor_sync(0xffffffffu, s,  o);
        sq += __shfl_xor_sync(0xffffffffu, sq, o);
    }
    __shared__ float ss[8], ssq[8];
    __shared__ float s_mu, s_r;
    if ((tid & 31) == 0) { ss[tid >> 5] = s; ssq[tid >> 5] = sq; }
    __syncthreads();
    if (tid == 0) {
        float S = 0.f, Q = 0.f;
        #pragma unroll
        for (int i = 0; i < 8; i++) { S += ss[i]; Q += ssq[i]; }
        float mu  = S * (1.0f / DMODEL);
        float var = Q * (1.0f / DMODEL) - mu * mu;
        s_mu = mu;
        s_r  = rsqrtf(var + 1e-5f);
    }
    __syncthreads();
    float mu = s_mu, r = s_r;
    float4 w4 = ((const float4*)w)[tid];
    float4 b4 = ((const float4*)b)[tid];
    __half2* orow = (__half2*)(out + (size_t)row * DMODEL);
    orow[tid * 2 + 0] = __floats2half2_rn((v.x - mu) * r * w4.x + b4.x,
                                          (v.y - mu) * r * w4.y + b4.y);
    orow[tid * 2 + 1] = __floats2half2_rn((v.z - mu) * r * w4.z + b4.z,
                                          (v.w - mu) * r * w4.w + b4.w);
}

// ---------------------------------------------------------------------------
// fp16 mma.sync GEMM: A[M][K] half, Bt[N][K] half, fp32 accum.
// modes: 0 half out; 1 fp32 relu(v)+res; 2 half gelu(v); 3 fp32 v+res
// CTA 128x128, 8 warps 2m x 4n (64x32), BK=64, 2-stage cp.async.
// smem tiles [128][72] halves (144B rows, ldmatrix conflict-free).
// ---------------------------------------------------------------------------
#define HP 72
#define HTILE (128 * HP)
#define HSTG  (2 * HTILE)
#define GEMM_SMEM_BYTES (2 * HSTG * 2)

__global__ __launch_bounds__(256, 2) void tgemm_kernel(
    const __half* __restrict__ A, const __half* __restrict__ Bt,
    const float* __restrict__ bias, const float* __restrict__ res,
    float* __restrict__ C, int M, int N, int K, int mode)
{
    extern __shared__ __half smh[];
    uint32_t smb = s2u(smh);

    int tid  = threadIdx.x;
    int lane = tid & 31;
    int wid  = tid >> 5;
    int wm   = wid >> 2;
    int wn   = wid & 3;
    int lr   = lane >> 2;
    int lc   = lane & 3;

    int bn = blockIdx.x * 128;
    int bm = blockIdx.y * 128;

    int mat = lane >> 3;
    uint32_t aoff = (uint32_t)(((wm * 64 + (lane & 7) + ((mat & 1) << 3)) * HP
                               + ((mat >> 1) << 3)) * 2);
    uint32_t boff = (uint32_t)(((wn * 32 + ((mat >> 1) << 3) + (lane & 7)) * HP
                               + ((mat & 1) << 3)) * 2);

    float acc[4][4][4];
    #pragma unroll
    for (int i = 0; i < 4; i++)
        #pragma unroll
        for (int j = 0; j < 4; j++)
            #pragma unroll
            for (int q = 0; q < 4; q++) acc[i][j][q] = 0.f;

    int NS = K >> 6;

    #pragma unroll
    for (int st = 0; st < 2; st++) {
        uint32_t Ab = smb + (uint32_t)st * HSTG * 2;
        uint32_t Bb = Ab + HTILE * 2;
        int k0 = st * 64;
        #pragma unroll
        for (int t = 0; t < 4; t++) {
            int idx = tid + t * 256;
            int r = idx >> 3, ch = idx & 7;
            cpa16(Ab + (uint32_t)(r * HP + ch * 8) * 2,
                  A + (size_t)(bm + r) * K + k0 + ch * 8);
            cpa16(Bb + (uint32_t)(r * HP + ch * 8) * 2,
                  Bt + (size_t)(bn + r) * K + k0 + ch * 8);
        }
        asm volatile("cp.async.commit_group;" ::: "memory");
    }

    for (int s = 0; s < NS; s++) {
        if (s + 1 < NS) asm volatile("cp.async.wait_group 1;" ::: "memory");
        else            asm volatile("cp.async.wait_group 0;" ::: "memory");
        __syncthreads();

        uint32_t Ab = smb + (uint32_t)(s & 1) * HSTG * 2;
        uint32_t Bb = Ab + HTILE * 2;

        #pragma unroll
        for (int kk = 0; kk < 4; kk++) {
            uint32_t af[4][4];
            #pragma unroll
            for (int mt = 0; mt < 4; mt++) {
                asm volatile(
                    "ldmatrix.sync.aligned.m8n8.x4.shared.b16 {%0,%1,%2,%3}, [%4];"
                    : "=r"(af[mt][0]), "=r"(af[mt][1]), "=r"(af[mt][2]), "=r"(af[mt][3])
                    : "r"(Ab + aoff + (uint32_t)((mt * 16 * HP + kk * 16) * 2)));
            }
            uint32_t bf[4][2];
            #pragma unroll
            for (int p = 0; p < 2; p++) {
                asm volatile(
                    "ldmatrix.sync.aligned.m8n8.x4.shared.b16 {%0,%1,%2,%3}, [%4];"
                    : "=r"(bf[2*p][0]), "=r"(bf[2*p][1]),
                      "=r"(bf[2*p+1][0]), "=r"(bf[2*p+1][1])
                    : "r"(Bb + boff + (uint32_t)((p * 16 * HP + kk * 16) * 2)));
            }
            #pragma unroll
            for (int mt = 0; mt < 4; mt++)
                #pragma unroll
                for (int nt = 0; nt < 4; nt++) {
                    asm volatile(
                        "mma.sync.aligned.m16n8k16.row.col.f32.f16.f16.f32 "
                        "{%0,%1,%2,%3}, {%4,%5,%6,%7}, {%8,%9}, {%0,%1,%2,%3};"
                        : "+f"(acc[mt][nt][0]), "+f"(acc[mt][nt][1]),
                          "+f"(acc[mt][nt][2]), "+f"(acc[mt][nt][3])
                        : "r"(af[mt][0]), "r"(af[mt][1]), "r"(af[mt][2]), "r"(af[mt][3]),
                          "r"(bf[nt][0]), "r"(bf[nt][1]));
                }
        }

        __syncthreads();
        if (s + 2 < NS) {
            uint32_t Ab2 = smb + (uint32_t)(s & 1) * HSTG * 2;
            uint32_t Bb2 = Ab2 + HTILE * 2;
            int k0 = (s + 2) * 64;
            #pragma unroll
            for (int t = 0; t < 4; t++) {
                int idx = tid + t * 256;
                int r = idx >> 3, ch = idx & 7;
                cpa16(Ab2 + (uint32_t)(r * HP + ch * 8) * 2,
                      A + (size_t)(bm + r) * K + k0 + ch * 8);
                cpa16(Bb2 + (uint32_t)(r * HP + ch * 8) * 2,
                      Bt + (size_t)(bn + r) * K + k0 + ch * 8);
            }
            asm volatile("cp.async.commit_group;" ::: "memory");
        }
    }

    // ---- epilogue ----
    #pragma unroll
    for (int mt = 0; mt < 4; mt++) {
        #pragma unroll
        for (int half_ = 0; half_ < 2; half_++) {
            int row = bm + wm * 64 + mt * 16 + lr + half_ * 8;
            const float* rr = (mode == 1 || mode == 3) ? (res + (size_t)row * N) : nullptr;
            #pragma unroll
            for (int nt = 0; nt < 4; nt++) {
                int col = bn + wn * 32 + nt * 8 + lc * 2;
                float v0 = acc[mt][nt][half_ * 2 + 0] + bias[col];
                float v1 = acc[mt][nt][half_ * 2 + 1] + bias[col + 1];
                if (mode == 0) {
                    *(__half2*)((__half*)C + (size_t)row * N + col) = __floats2half2_rn(v0, v1);
                } else if (mode == 1) {
                    float2 o; o.x = fmaxf(v0, 0.f) + rr[col]; o.y = fmaxf(v1, 0.f) + rr[col + 1];
                    *(float2*)(C + (size_t)row * N + col) = o;
                } else if (mode == 2) {
                    v0 = 0.5f * v0 * (1.f + erff(v0 * 0.70710678118654752f));
                    v1 = 0.5f * v1 * (1.f + erff(v1 * 0.70710678118654752f));
                    *(__half2*)((__half*)C + (size_t)row * N + col) = __floats2half2_rn(v0, v1);
                } else {
                    float2 o; o.x = v0 + rr[col]; o.y = v1 + rr[col + 1];
                    *(float2*)(C + (size_t)row * N + col) = o;
                }
            }
        }
    }
}

// ---------------------------------------------------------------------------
// Flash attention, fp16 mma. grid (8, 128), 256 thr, warp = 16 q-rows.
// P stays in registers (C-frag -> A-frag conversion). V via ldmatrix.trans.
// smem: sQ[128][72], sK[64][72], sV[64][72] halves.
// ---------------------------------------------------------------------------
#define SP 72
#define SQ_OFF 0
#define SK_OFF (128 * SP)
#define SV_OFF (SK_OFF + 64 * SP)
#define ATTN_SMEM_BYTES ((SV_OFF + 64 * SP) * 2)

__global__ __launch_bounds__(256, 2) void attn_kernel(
    const __half* __restrict__ QKV, __half* __restrict__ Og)
{
    extern __shared__ __half smh[];
    __half* sQ = smh + SQ_OFF;
    __half* sK = smh + SK_OFF;
    __half* sV = smh + SV_OFF;

    int bh = blockIdx.y;
    int b  = bh >> 4;
    int h  = bh & 15;
    int q0 = blockIdx.x * 128;

    size_t base = (size_t)b * 1024 * 3072;
    const __half* Qb = QKV + base + h * DKH;
    const __half* Kb = QKV + base + 1024 + h * DKH;
    const __half* Vb = QKV + base + 2048 + h * DKH;
    __half* Ob = Og + (size_t)b * 1024 * DMODEL + h * DKH;

    int tid  = threadIdx.x;
    int lane = tid & 31;
    int wid  = tid >> 5;
    int lr   = lane >> 2;
    int lc   = lane & 3;
    int mat  = lane >> 3;

    uint32_t sQb = s2u(sQ);
    uint32_t sKb = s2u(sK);
    uint32_t sVb = s2u(sV);
    uint32_t aoffQ = (uint32_t)(((wid * 16 + (lane & 7) + ((mat & 1) << 3)) * SP
                                + ((mat >> 1) << 3)) * 2);
    uint32_t koff  = (uint32_t)(((((mat >> 1) << 3) + (lane & 7)) * SP
                                + ((mat & 1) << 3)) * 2);
    uint32_t voff  = (uint32_t)(((((mat & 1) << 3) + (lane & 7)) * SP
                                + ((mat >> 1) << 3)) * 2);

    // load Q tile (128 x 64 halves)
    #pragma unroll
    for (int it = 0; it < 4; it++) {
        int idx = tid + it * 256;
        int r = idx >> 3, ch = idx & 7;
        *(uint4*)(sQ + r * SP + ch * 8) =
            *(const uint4*)(Qb + (size_t)(q0 + r) * 3072 + ch * 8);
    }

    float m0 = -1e30f, m1 = -1e30f, l0 = 0.f, l1 = 0.f;
    float o[8][4];
    #pragma unroll
    for (int nt = 0; nt < 8; nt++)
        #pragma unroll
        for (int q = 0; q < 4; q++) o[nt][q] = 0.f;

    for (int kt = 0; kt < 16; kt++) {
        __syncthreads();
        #pragma unroll
        for (int it = 0; it < 2; it++) {
            int idx = tid + it * 256;
            int r = idx >> 3, ch = idx & 7;
            *(uint4*)(sK + r * SP + ch * 8) =
                *(const uint4*)(Kb + (size_t)(kt * 64 + r) * 3072 + ch * 8);
            *(uint4*)(sV + r * SP + ch * 8) =
                *(const uint4*)(Vb + (size_t)(kt * 64 + r) * 3072 + ch * 8);
        }
        __syncthreads();

        // S = Q K^T : 16 x 64 per warp
        float sc[8][4];
        #pragma unroll
        for (int nt = 0; nt < 8; nt++)
            #pragma unroll
            for (int q = 0; q < 4; q++) sc[nt][q] = 0.f;

        #pragma unroll
        for (int kk = 0; kk < 4; kk++) {
            uint32_t a0, a1, a2, a3;
            asm volatile(
                "ldmatrix.sync.aligned.m8n8.x4.shared.b16 {%0,%1,%2,%3}, [%4];"
                : "=r"(a0), "=r"(a1), "=r"(a2), "=r"(a3)
                : "r"(sQb + aoffQ + (uint32_t)(kk * 32)));
            uint32_t kf[8][2];
            #pragma unroll
            for (int p = 0; p < 4; p++) {
                asm volatile(
                    "ldmatrix.sync.aligned.m8n8.x4.shared.b16 {%0,%1,%2,%3}, [%4];"
                    : "=r"(kf[2*p][0]), "=r"(kf[2*p][1]),
                      "=r"(kf[2*p+1][0]), "=r"(kf[2*p+1][1])
                    : "r"(sKb + koff + (uint32_t)((p * 16 * SP + kk * 16) * 2)));
            }
            #pragma unroll
            for (int nt = 0; nt < 8; nt++) {
                asm volatile(
                    "mma.sync.aligned.m16n8k16.row.col.f32.f16.f16.f32 "
                    "{%0,%1,%2,%3}, {%4,%5,%6,%7}, {%8,%9}, {%0,%1,%2,%3};"
                    : "+f"(sc[nt][0]), "+f"(sc[nt][1]), "+f"(sc[nt][2]), "+f"(sc[nt][3])
                    : "r"(a0), "r"(a1), "r"(a2), "r"(a3),
                      "r"(kf[nt][0]), "r"(kf[nt][1]));
            }
        }

        // online softmax (rows lr and lr+8)
        float x0 = -1e30f, x1 = -1e30f;
        #pragma unroll
        for (int nt = 0; nt < 8; nt++) {
            x0 = fmaxf(x0, fmaxf(sc[nt][0], sc[nt][1]));
            x1 = fmaxf(x1, fmaxf(sc[nt][2], sc[nt][3]));
        }
        x0 = fmaxf(x0, __shfl_xor_sync(0xffffffffu, x0, 1));
        x0 = fmaxf(x0, __shfl_xor_sync(0xffffffffu, x0, 2));
        x1 = fmaxf(x1, __shfl_xor_sync(0xffffffffu, x1, 1));
        x1 = fmaxf(x1, __shfl_xor_sync(0xffffffffu, x1, 2));
        float mn0 = fmaxf(m0, x0), mn1 = fmaxf(m1, x1);
        float al0 = __expf(m0 - mn0), al1 = __expf(m1 - mn1);
        float su0 = 0.f, su1 = 0.f;
        #pragma unroll
        for (int nt = 0; nt < 8; nt++) {
            sc[nt][0] = __expf(sc[nt][0] - mn0);
            sc[nt][1] = __expf(sc[nt][1] - mn0);
            sc[nt][2] = __expf(sc[nt][2] - mn1);
            sc[nt][3] = __expf(sc[nt][3] - mn1);
            su0 += sc[nt][0] + sc[nt][1];
            su1 += sc[nt][2] + sc[nt][3];
            o[nt][0] *= al0; o[nt][1] *= al0;
            o[nt][2] *= al1; o[nt][3] *= al1;
        }
        su0 += __shfl_xor_sync(0xffffffffu, su0, 1);
        su0 += __shfl_xor_sync(0xffffffffu, su0, 2);
        su1 += __shfl_xor_sync(0xffffffffu, su1, 1);
        su1 += __shfl_xor_sync(0xffffffffu, su1, 2);
        l0 = l0 * al0 + su0;
        l1 = l1 * al1 + su1;
        m0 = mn0; m1 = mn1;

        // O += P @ V : P from registers (C-frag -> A-frag), V via ldmatrix.trans
        #pragma unroll
        for (int kk = 0; kk < 4; kk++) {
            uint32_t pa0 = h2u(__floats2half2_rn(sc[2*kk][0],   sc[2*kk][1]));
            uint32_t pa1 = h2u(__floats2half2_rn(sc[2*kk][2],   sc[2*kk][3]));
            uint32_t pa2 = h2u(__floats2half2_rn(sc[2*kk+1][0], sc[2*kk+1][1]));
            uint32_t pa3 = h2u(__floats2half2_rn(sc[2*kk+1][2], sc[2*kk+1][3]));
            #pragma unroll
            for (int p = 0; p < 4; p++) {
                uint32_t vf[2][2];
                asm volatile(
                    "ldmatrix.sync.aligned.m8n8.x4.trans.shared.b16 {%0,%1,%2,%3}, [%4];"
                    : "=r"(vf[0][0]), "=r"(vf[0][1]), "=r"(vf[1][0]), "=r"(vf[1][1])
                    : "r"(sVb + voff + (uint32_t)((kk * 16 * SP + p * 16) * 2)));
                #pragma unroll
                for (int g = 0; g < 2; g++) {
                    int nt = p * 2 + g;
                    asm volatile(
                        "mma.sync.aligned.m16n8k16.row.col.f32.f16.f16.f32 "
                        "{%0,%1,%2,%3}, {%4,%5,%6,%7}, {%8,%9}, {%0,%1,%2,%3};"
                        : "+f"(o[nt][0]), "+f"(o[nt][1]), "+f"(o[nt][2]), "+f"(o[nt][3])
                        : "r"(pa0), "r"(pa1), "r"(pa2), "r"(pa3),
                          "r"(vf[g][0]), "r"(vf[g][1]));
                }
            }
        }
    }

    // epilogue: normalize, store half
    float inv0 = 1.f / l0, inv1 = 1.f / l1;
    int row0 = q0 + wid * 16 + lr;
    int row1 = row0 + 8;
    #pragma unroll
    for (int nt = 0; nt < 8; nt++) {
        int col = nt * 8 + lc * 2;
        *(__half2*)(Ob + (size_t)row0 * DMODEL + col) =
            __floats2half2_rn(o[nt][0] * inv0, o[nt][1] * inv0);
        *(__half2*)(Ob + (size_t)row1 * DMODEL + col) =
            __floats2half2_rn(o[nt][2] * inv1, o[nt][3] * inv1);
    }
}

// ---------------------------------------------------------------------------
// Host launcher
// ---------------------------------------------------------------------------
extern "C" void kernel_launch(void* const* d_in, const int* in_sizes, int n_in,
                              void* d_out, int out_size)
{
    const float* x     = (const float*)d_in[0];
    const float* ln1_w = (const float*)d_in[1];
    const float* ln1_b = (const float*)d_in[2];
    const float* wq    = (const float*)d_in[3];
    const float* bq    = (const float*)d_in[4];
    const float* wk    = (const float*)d_in[5];
    const float* bk    = (const float*)d_in[6];
    const float* wv    = (const float*)d_in[7];
    const float* bv    = (const float*)d_in[8];
    const float* wo    = (const float*)d_in[9];
    const float* bo    = (const float*)d_in[10];
    const float* ln2_w = (const float*)d_in[11];
    const float* ln2_b = (const float*)d_in[12];
    const float* w1    = (const float*)d_in[13];
    const float* b1    = (const float*)d_in[14];
    const float* w2    = (const float*)d_in[15];
    const float* b2    = (const float*)d_in[16];

    __half *p_h, *p_qkv, *p_ctx, *p_h2, *p_ff, *p_wh;
    float *p_out1, *p_bqkv;
    cudaGetSymbolAddress((void**)&p_h,    g_h);
    cudaGetSymbolAddress((void**)&p_qkv,  g_qkv);
    cudaGetSymbolAddress((void**)&p_ctx,  g_ctx);
    cudaGetSymbolAddress((void**)&p_out1, g_out1);
    cudaGetSymbolAddress((void**)&p_h2,   g_h2);
    cudaGetSymbolAddress((void**)&p_ff,   g_ff);
    cudaGetSymbolAddress((void**)&p_wh,   g_wh);
    cudaGetSymbolAddress((void**)&p_bqkv, g_bqkv);

    const int MB = 1024 * 1024;
    __half* wqkvT = p_wh;               // [3072][1024]
    __half* woT   = p_wh + 3 * MB;      // [1024][1024]
    __half* w1T   = p_wh + 4 * MB;      // [4096][1024]
    __half* w2T   = p_wh + 8 * MB;      // [1024][4096]

    cudaFuncSetAttribute(attn_kernel, cudaFuncAttributeMaxDynamicSharedMemorySize,
                         ATTN_SMEM_BYTES);
    cudaFuncSetAttribute(tgemm_kernel, cudaFuncAttributeMaxDynamicSharedMemorySize,
                         GEMM_SMEM_BYTES);

    // 0) weight prep (transpose + fp16; Q scale folded)
    transw_kernel<<<dim3(32, 32), dim3(32, 8)>>>(wq, wqkvT, 1024, 1024, 0, 0.125f);
    transw_kernel<<<dim3(32, 32), dim3(32, 8)>>>(wk, wqkvT, 1024, 1024, 1024, 1.f);
    transw_kernel<<<dim3(32, 32), dim3(32, 8)>>>(wv, wqkvT, 1024, 1024, 2048, 1.f);
    transw_kernel<<<dim3(32, 32), dim3(32, 8)>>>(wo, woT, 1024, 1024, 0, 1.f);
    transw_kernel<<<dim3(128, 32), dim3(32, 8)>>>(w1, w1T, 1024, 4096, 0, 1.f);
    transw_kernel<<<dim3(32, 128), dim3(32, 8)>>>(w2, w2T, 4096, 1024, 0, 1.f);
    packb_kernel<<<12, 256>>>(bq, bk, bv, p_bqkv);

    // 1) ln1 -> half
    ln_kernel<<<TOK, 256>>>(x, ln1_w, ln1_b, p_h);
    // 2) fused QKV projection (half out)
    tgemm_kernel<<<dim3(24, 64), 256, GEMM_SMEM_BYTES>>>(
        p_h, wqkvT, p_bqkv, nullptr, (float*)p_qkv, TOK, 3 * DMODEL, DMODEL, 0);
    // 3) attention (fp16 mma, half out)
    attn_kernel<<<dim3(8, 128), 256, ATTN_SMEM_BYTES>>>(p_qkv, p_ctx);
    // 4) out proj + relu + residual(x) -> fp32 out1
    tgemm_kernel<<<dim3(8, 64), 256, GEMM_SMEM_BYTES>>>(
        p_ctx, woT, bo, x, p_out1, TOK, DMODEL, DMODEL, 1);
    // 5) ln2 -> half
    ln_kernel<<<TOK, 256>>>(p_out1, ln2_w, ln2_b, p_h2);
    // 6) MLP up + gelu (half out)
    tgemm_kernel<<<dim3(32, 64), 256, GEMM_SMEM_BYTES>>>(
        p_h2, w1T, b1, nullptr, (float*)p_ff, TOK, DMLP, DMODEL, 2);
    // 7) MLP down + residual(out1) -> fp32 d_out
    tgemm_kernel<<<dim3(8, 64), 256, GEMM_SMEM_BYTES>>>(
        p_ff, w2T, b2, p_out1, (float*)d_out, TOK, DMODEL, DMLP, 3);
}